// round 2
// baseline (speedup 1.0000x reference)
#include <cuda_runtime.h>
#include <math.h>

#define D_MODEL   1024
#define D_STATE   64
#define D_CONV    4
#define D_INNER   2048
#define NHEADS    32
#define HEADDIM   64
#define D_PROJ    8224          // 2*D_INNER + NHEADS*(2*D_STATE+1)
#define BATCH     2
#define SEQLEN    1024
#define NTOK      (BATCH*SEQLEN)   // 2048

// Scratch (static device allocations are allowed; cudaMalloc is not)
__device__ float g_proj [NTOK * D_PROJ];    // 2048 x 8224
__device__ float g_xconv[NTOK * D_INNER];   // 2048 x 2048  (post conv + silu)
__device__ float g_y    [NTOK * D_INNER];   // 2048 x 2048  (gated scan output)

// ----------------------------------------------------------------------------
// SGEMM (NT): C[M,N] = A[M,K] * B[N,K]^T    (both A and B are K-contiguous)
// 128x128 block tile, BK=16, 8x8 per-thread micro-tile, 256 threads.
// Requires: M % 128 == 0, K % 16 == 0.  N is guarded (load + store).
// ----------------------------------------------------------------------------
#define BM 128
#define BN 128
#define BK 16
#define TM 8
#define TN 8

__global__ __launch_bounds__(256, 2)
void sgemm_nt(const float* __restrict__ A, const float* __restrict__ B,
              float* __restrict__ C, int M, int N, int K)
{
    __shared__ float sA[BK][BM];
    __shared__ float sB[BK][BN];

    const int tid = threadIdx.x;
    const int m0  = blockIdx.y * BM;
    const int n0  = blockIdx.x * BN;

    // load mapping: 256 threads, each loads 2x float4 from A and 2x from B
    const int ldRow = tid >> 2;          // 0..63
    const int ldCol = (tid & 3) * 4;     // 0,4,8,12

    // compute mapping: 16x16 thread grid, 8x8 micro-tile
    const int rm = (tid >> 4) * TM;      // row offset within tile
    const int rn = (tid & 15) * TN;      // col offset within tile

    float acc[TM][TN];
    #pragma unroll
    for (int i = 0; i < TM; i++)
        #pragma unroll
        for (int j = 0; j < TN; j++) acc[i][j] = 0.f;

    for (int k0 = 0; k0 < K; k0 += BK) {
        // ---- load A tile (always in-bounds: M,K multiples of tile dims) ----
        #pragma unroll
        for (int p = 0; p < 2; p++) {
            int row = p * 64 + ldRow;
            float4 v = *reinterpret_cast<const float4*>(
                &A[(size_t)(m0 + row) * K + k0 + ldCol]);
            sA[ldCol + 0][row] = v.x;
            sA[ldCol + 1][row] = v.y;
            sA[ldCol + 2][row] = v.z;
            sA[ldCol + 3][row] = v.w;
        }
        // ---- load B tile (guard n) ----
        #pragma unroll
        for (int p = 0; p < 2; p++) {
            int row = p * 64 + ldRow;
            float4 v = make_float4(0.f, 0.f, 0.f, 0.f);
            if (n0 + row < N)
                v = *reinterpret_cast<const float4*>(
                    &B[(size_t)(n0 + row) * K + k0 + ldCol]);
            sB[ldCol + 0][row] = v.x;
            sB[ldCol + 1][row] = v.y;
            sB[ldCol + 2][row] = v.z;
            sB[ldCol + 3][row] = v.w;
        }
        __syncthreads();

        #pragma unroll
        for (int kk = 0; kk < BK; kk++) {
            float a[TM], b[TN];
            *reinterpret_cast<float4*>(&a[0]) = *reinterpret_cast<const float4*>(&sA[kk][rm]);
            *reinterpret_cast<float4*>(&a[4]) = *reinterpret_cast<const float4*>(&sA[kk][rm + 4]);
            *reinterpret_cast<float4*>(&b[0]) = *reinterpret_cast<const float4*>(&sB[kk][rn]);
            *reinterpret_cast<float4*>(&b[4]) = *reinterpret_cast<const float4*>(&sB[kk][rn + 4]);
            #pragma unroll
            for (int i = 0; i < TM; i++)
                #pragma unroll
                for (int j = 0; j < TN; j++)
                    acc[i][j] = fmaf(a[i], b[j], acc[i][j]);
        }
        __syncthreads();
    }

    // ---- store (guard n) ----
    #pragma unroll
    for (int i = 0; i < TM; i++) {
        size_t rowBase = (size_t)(m0 + rm + i) * N;
        #pragma unroll
        for (int j = 0; j < TN; j++) {
            int n = n0 + rn + j;
            if (n < N) C[rowBase + n] = acc[i][j];
        }
    }
}

// ----------------------------------------------------------------------------
// Depthwise causal conv(width 4) + bias + SiLU over x_inner = proj[:, :D_INNER]
// ----------------------------------------------------------------------------
__global__ void conv_silu_kernel(const float* __restrict__ proj,
                                 const float* __restrict__ conv_w,
                                 const float* __restrict__ conv_b,
                                 float* __restrict__ xconv)
{
    int idx = blockIdx.x * blockDim.x + threadIdx.x;
    if (idx >= NTOK * D_INNER) return;
    int c   = idx % D_INNER;
    int tok = idx / D_INNER;
    int b   = tok / SEQLEN;
    int t   = tok % SEQLEN;

    float acc = conv_b[c];
    #pragma unroll
    for (int j = 0; j < D_CONV; j++) {
        int tt = t - (D_CONV - 1) + j;
        if (tt >= 0)
            acc = fmaf(conv_w[c * D_CONV + j],
                       proj[(size_t)(b * SEQLEN + tt) * D_PROJ + c], acc);
    }
    float sig = 1.f / (1.f + expf(-acc));
    xconv[idx] = acc * sig;
}

// ----------------------------------------------------------------------------
// Selective scan: one block per (batch, head), 64 threads (one per head-dim d).
// Each thread keeps the 64-entry state column h[s] in registers.
// Fuses: +D*x skip, silu(z) gating. Writes g_y.
// ----------------------------------------------------------------------------
__global__ __launch_bounds__(HEADDIM)
void ssm_scan_kernel(const float* __restrict__ proj,
                     const float* __restrict__ xconv,
                     const float* __restrict__ A_log,
                     const float* __restrict__ Dp,
                     const float* __restrict__ dt_bias,
                     float* __restrict__ y)
{
    const int bh = blockIdx.x;            // 0..63
    const int b  = bh / NHEADS;
    const int n  = bh % NHEADS;
    const int d  = threadIdx.x;           // 0..63

    __shared__ float sh_dA[D_STATE];
    __shared__ float sh_dB[D_STATE];
    __shared__ float sh_C [D_STATE];
    __shared__ float sh_negA[D_STATE];

    sh_negA[d] = -expf(A_log[n * D_STATE + d]);

    float h[D_STATE];
    #pragma unroll
    for (int s = 0; s < D_STATE; s++) h[s] = 0.f;

    const float Dn  = Dp[n];
    const float dtb = dt_bias[n];
    __syncthreads();

    for (int t = 0; t < SEQLEN; t++) {
        const size_t tok = (size_t)(b * SEQLEN + t);
        const float* row = proj + tok * D_PROJ;
        const float* bc  = row + 2 * D_INNER + n * (2 * D_STATE + 1);

        // dt = softplus(dt_raw + dt_bias)  (computed redundantly by all threads)
        float dtr = bc[2 * D_STATE] + dtb;
        float dt  = fmaxf(dtr, 0.f) + log1pf(expf(-fabsf(dtr)));

        // thread d publishes entries for state index s = d
        sh_dA[d] = expf(sh_negA[d] * dt);
        sh_dB[d] = bc[d] * dt;
        sh_C[d]  = bc[D_STATE + d];

        float xv = xconv[tok * D_INNER + n * HEADDIM + d];
        __syncthreads();

        float acc = 0.f;
        #pragma unroll
        for (int s = 0; s < D_STATE; s++) {
            h[s] = fmaf(sh_dA[s], h[s], sh_dB[s] * xv);
            acc  = fmaf(sh_C[s], h[s], acc);
        }

        float yv = fmaf(Dn, xv, acc);
        float zv = row[D_INNER + n * HEADDIM + d];
        float sz = zv / (1.f + expf(-zv));
        y[tok * D_INNER + n * HEADDIM + d] = yv * sz;
        __syncthreads();   // protect shared arrays before next step's writes
    }
}

// ----------------------------------------------------------------------------
extern "C" void kernel_launch(void* const* d_in, const int* in_sizes, int n_in,
                              void* d_out, int out_size)
{
    const float* x       = (const float*)d_in[0];  // (2,1024,1024)
    const float* W_in    = (const float*)d_in[1];  // (8224,1024)
    const float* conv_w  = (const float*)d_in[2];  // (2048,1,4)
    const float* conv_b  = (const float*)d_in[3];  // (2048)
    const float* A_log   = (const float*)d_in[4];  // (32,64)
    const float* Dp      = (const float*)d_in[5];  // (32)
    const float* dt_bias = (const float*)d_in[6];  // (32)
    const float* W_out   = (const float*)d_in[7];  // (1024,2048)
    float* out = (float*)d_out;                    // (2,1024,1024)

    float* proj;  cudaGetSymbolAddress((void**)&proj,  g_proj);
    float* xconv; cudaGetSymbolAddress((void**)&xconv, g_xconv);
    float* yb;    cudaGetSymbolAddress((void**)&yb,    g_y);

    // 1) proj = x @ W_in^T : [2048,8224]
    {
        dim3 grid((D_PROJ + BN - 1) / BN, NTOK / BM);
        sgemm_nt<<<grid, 256>>>(x, W_in, proj, NTOK, D_PROJ, D_MODEL);
    }
    // 2) depthwise conv + silu
    {
        int total = NTOK * D_INNER;
        conv_silu_kernel<<<(total + 255) / 256, 256>>>(proj, conv_w, conv_b, xconv);
    }
    // 3) selective scan + skip + gate
    {
        ssm_scan_kernel<<<BATCH * NHEADS, HEADDIM>>>(proj, xconv, A_log, Dp, dt_bias, yb);
    }
    // 4) out = y @ W_out^T : [2048,1024]
    {
        dim3 grid(D_MODEL / BN, NTOK / BM);
        sgemm_nt<<<grid, 256>>>(yb, W_out, out, NTOK, D_MODEL, D_INNER);
    }
}

// round 8
// speedup vs baseline: 1.1653x; 1.1653x over previous
#include <cuda_runtime.h>
#include <cuda_bf16.h>
#include <math.h>
#include <stdint.h>

#define D_MODEL   1024
#define D_STATE   64
#define D_CONV    4
#define D_INNER   2048
#define NHEADS    32
#define HEADDIM   64
#define D_PROJ    8224
#define BATCH     2
#define SEQLEN    1024
#define NTOK      (BATCH*SEQLEN)     // 2048
#define NPROJ_PAD 8320               // D_PROJ padded to 65*128

// ---------------- scratch (static device allocations) ----------------------
__device__ float g_proj [(size_t)NTOK * D_PROJ];
__device__ float g_xconv[(size_t)NTOK * D_INNER];
__device__ __nv_bfloat16 g_x_hi  [(size_t)NTOK * D_MODEL];
__device__ __nv_bfloat16 g_x_lo  [(size_t)NTOK * D_MODEL];
__device__ __nv_bfloat16 g_Win_hi[(size_t)NPROJ_PAD * D_MODEL];
__device__ __nv_bfloat16 g_Win_lo[(size_t)NPROJ_PAD * D_MODEL];
__device__ __nv_bfloat16 g_Wout_hi[(size_t)D_MODEL * D_INNER];
__device__ __nv_bfloat16 g_Wout_lo[(size_t)D_MODEL * D_INNER];
__device__ __nv_bfloat16 g_y_hi  [(size_t)NTOK * D_INNER];
__device__ __nv_bfloat16 g_y_lo  [(size_t)NTOK * D_INNER];

// ---------------- helpers ---------------------------------------------------
__device__ __forceinline__ uint32_t smem_u32(const void* p) {
    uint32_t a;
    asm("{ .reg .u64 t; cvta.to.shared.u64 t, %1; cvt.u32.u64 %0, t; }" : "=r"(a) : "l"(p));
    return a;
}
#define CP_ASYNC16(dst, src) \
    asm volatile("cp.async.cg.shared.global [%0], [%1], 16;" :: "r"(dst), "l"(src) : "memory")
#define CP_COMMIT() asm volatile("cp.async.commit_group;" ::: "memory")

__device__ __forceinline__ void ldmatrix_x4(uint32_t* r, uint32_t addr) {
    asm volatile("ldmatrix.sync.aligned.m8n8.x4.shared.b16 {%0,%1,%2,%3}, [%4];"
        : "=r"(r[0]), "=r"(r[1]), "=r"(r[2]), "=r"(r[3]) : "r"(addr));
}
__device__ __forceinline__ void mma16816(float* c, const uint32_t* a, const uint32_t* b) {
    asm volatile("mma.sync.aligned.m16n8k16.row.col.f32.bf16.bf16.f32 "
        "{%0,%1,%2,%3}, {%4,%5,%6,%7}, {%8,%9}, {%0,%1,%2,%3};"
        : "+f"(c[0]), "+f"(c[1]), "+f"(c[2]), "+f"(c[3])
        : "r"(a[0]), "r"(a[1]), "r"(a[2]), "r"(a[3]), "r"(b[0]), "r"(b[1]));
}

// ---------------- fp32 -> bf16 hi/lo split ----------------------------------
__global__ void split_bf16(const float* __restrict__ in, __nv_bfloat16* __restrict__ hi,
                           __nv_bfloat16* __restrict__ lo, int n_in, int n_tot)
{
    int i = blockIdx.x * blockDim.x + threadIdx.x;
    if (i >= n_tot) return;
    float v = (i < n_in) ? in[i] : 0.f;
    __nv_bfloat16 h = __float2bfloat16(v);
    hi[i] = h;
    lo[i] = __float2bfloat16(v - __bfloat162float(h));
}

// ---------------- split-bf16 tensor-core GEMM (NT) via mma.sync --------------
// C[M,N] = A[M,K]*B[N,K]^T with A,B as bf16 hi/lo pairs, fp32 accumulate.
// CTA tile 128x128, BK=32, 8 warps (warp tile 32x64), cp.async double buffer.
// smem rows padded to 80B (32 bf16 + 8 pad) -> conflict-free ldmatrix.
#define ROWB    80
#define TILE_B  (128 * ROWB)          // 10240
#define STAGE_B (4 * TILE_B)          // Ah, Al, Bh, Bl
#define GEMM_SMEM (2 * STAGE_B)       // 81920

__global__ __launch_bounds__(256, 2)
void gemm_mma(const __nv_bfloat16* __restrict__ Ah, const __nv_bfloat16* __restrict__ Al,
              const __nv_bfloat16* __restrict__ Bh, const __nv_bfloat16* __restrict__ Bl,
              float* __restrict__ C, int M, int N, int K)
{
    extern __shared__ char smem[];
    const uint32_t sb = smem_u32(smem);
    const int tid  = threadIdx.x;
    const int lane = tid & 31;
    const int wid  = tid >> 5;
    const int wm   = wid & 3;          // 4 warps over M (32 rows each)
    const int wn   = wid >> 2;         // 2 warps over N (64 cols each)

    const int m0 = blockIdx.y * 128;
    const int n0 = blockIdx.x * 128;
    const int T  = K / 32;

    const __nv_bfloat16* gsrc[4] = {Ah, Al, Bh, Bl};
    const int grow[4] = {m0, m0, n0, n0};

    // stage loader: 4 tiles x 128 rows x 4 x 16B chunks
    const int lr = tid >> 2;          // 0..63
    const int lc = tid & 3;           // chunk 0..3
    auto load_stage = [&](int stg, int k0) {
        uint32_t base = sb + stg * STAGE_B;
        #pragma unroll
        for (int ts = 0; ts < 4; ts++) {
            const __nv_bfloat16* g = gsrc[ts] + (size_t)(grow[ts] + lr) * K + k0 + lc * 8;
            uint32_t dst = base + ts * TILE_B + lr * ROWB + lc * 16;
            CP_ASYNC16(dst, g);
            CP_ASYNC16(dst + 64 * ROWB, g + (size_t)64 * K);
        }
    };

    load_stage(0, 0);
    CP_COMMIT();

    float acc[2][8][4];
    #pragma unroll
    for (int i = 0; i < 2; i++)
        #pragma unroll
        for (int j = 0; j < 8; j++)
            #pragma unroll
            for (int k = 0; k < 4; k++) acc[i][j][k] = 0.f;

    // ldmatrix per-lane address components
    const int a_row = wm * 32 + (lane & 15);
    const int a_k   = (lane >> 4) << 3;                      // 0 / 8
    const int b_row = wn * 64 + (lane & 7) + ((lane & 16) >> 1);
    const int b_k   = lane & 8;                              // 0 / 8

    for (int t = 0; t < T; t++) {
        if (t + 1 < T) {
            load_stage((t + 1) & 1, (t + 1) * 32);
            CP_COMMIT();
            asm volatile("cp.async.wait_group 1;" ::: "memory");
        } else {
            asm volatile("cp.async.wait_group 0;" ::: "memory");
        }
        __syncthreads();

        const uint32_t st = sb + (t & 1) * STAGE_B;
        #pragma unroll
        for (int kk = 0; kk < 32; kk += 16) {
            #pragma unroll
            for (int sp = 0; sp < 3; sp++) {
                // sp0: Ah*Bh, sp1: Ah*Bl, sp2: Al*Bh
                const uint32_t Ab = st + ((sp == 2) ? TILE_B : 0);
                const uint32_t Bb = st + 2 * TILE_B + ((sp == 1) ? TILE_B : 0);
                uint32_t a[2][4];
                #pragma unroll
                for (int mf = 0; mf < 2; mf++)
                    ldmatrix_x4(a[mf], Ab + (a_row + mf * 16) * ROWB + (kk + a_k) * 2);
                uint32_t b[8][2];
                #pragma unroll
                for (int nb = 0; nb < 4; nb++) {
                    uint32_t r[4];
                    // non-trans: B stored [N,K] (K contiguous) is already
                    // col-major KxN for mma row.col
                    ldmatrix_x4(r, Bb + (b_row + nb * 16) * ROWB + (kk + b_k) * 2);
                    b[nb * 2][0] = r[0]; b[nb * 2][1] = r[1];
                    b[nb * 2 + 1][0] = r[2]; b[nb * 2 + 1][1] = r[3];
                }
                #pragma unroll
                for (int mf = 0; mf < 2; mf++)
                    #pragma unroll
                    for (int nf = 0; nf < 8; nf++)
                        mma16816(acc[mf][nf], a[mf], b[nf]);
            }
        }
        __syncthreads();
    }

    // epilogue
    #pragma unroll
    for (int mf = 0; mf < 2; mf++) {
        const int r0 = m0 + wm * 32 + mf * 16 + (lane >> 2);
        #pragma unroll
        for (int nf = 0; nf < 8; nf++) {
            const int col = n0 + wn * 64 + nf * 8 + (lane & 3) * 2;
            if (col < N) {
                float2 v0 = make_float2(acc[mf][nf][0], acc[mf][nf][1]);
                float2 v1 = make_float2(acc[mf][nf][2], acc[mf][nf][3]);
                *reinterpret_cast<float2*>(&C[(size_t)r0 * N + col]) = v0;
                *reinterpret_cast<float2*>(&C[(size_t)(r0 + 8) * N + col]) = v1;
            }
        }
    }
}

// ---------------- depthwise causal conv(4) + bias + SiLU ---------------------
__global__ void conv_silu_kernel(const float* __restrict__ proj,
                                 const float* __restrict__ conv_w,
                                 const float* __restrict__ conv_b,
                                 float* __restrict__ xconv)
{
    int idx = blockIdx.x * blockDim.x + threadIdx.x;
    if (idx >= NTOK * D_INNER) return;
    int c   = idx % D_INNER;
    int tok = idx / D_INNER;
    int b   = tok / SEQLEN;
    int t   = tok % SEQLEN;

    float acc = conv_b[c];
    #pragma unroll
    for (int j = 0; j < D_CONV; j++) {
        int tt = t - (D_CONV - 1) + j;
        if (tt >= 0)
            acc = fmaf(conv_w[c * D_CONV + j],
                       proj[(size_t)(b * SEQLEN + tt) * D_PROJ + c], acc);
    }
    float sig = 1.f / (1.f + expf(-acc));
    xconv[idx] = acc * sig;
}

// ---------------- selective scan ---------------------------------------------
// 128 blocks: block = (bh, d-half). 128 threads: d_local = tid>>2 (32 lanes),
// q = tid&3 owns states q*16..q*16+15 (16-entry state column in registers).
// One __syncthreads per step (double-buffered coefficient arrays).
__global__ __launch_bounds__(128)
void ssm_scan_kernel(const float* __restrict__ proj,
                     const float* __restrict__ xconv,
                     const float* __restrict__ A_log,
                     const float* __restrict__ Dp,
                     const float* __restrict__ dt_bias,
                     __nv_bfloat16* __restrict__ y_hi,
                     __nv_bfloat16* __restrict__ y_lo)
{
    const int bh2 = blockIdx.x;           // 0..127
    const int bh  = bh2 >> 1;
    const int dg  = bh2 & 1;              // which 32-lane d-half
    const int b   = bh / NHEADS;
    const int n   = bh % NHEADS;
    const int tid = threadIdx.x;
    const int dl  = tid >> 2;             // 0..31
    const int q   = tid & 3;              // state quarter
    const int d   = dg * 32 + dl;

    __shared__ float sA[2][D_STATE];
    __shared__ float sB[2][D_STATE];
    __shared__ float sC[2][D_STATE];
    __shared__ float s_negA[D_STATE];

    if (tid < D_STATE) s_negA[tid] = -expf(A_log[n * D_STATE + tid]);

    float h[16];
    #pragma unroll
    for (int i = 0; i < 16; i++) h[i] = 0.f;

    const float Dn  = Dp[n];
    const float dtb = dt_bias[n];
    __syncthreads();

    int buf = 0;
    const int s0 = q * 16;
    for (int t = 0; t < SEQLEN; t++) {
        const size_t tok = (size_t)(b * SEQLEN + t);
        const float* row = proj + tok * D_PROJ;
        const float* bc  = row + 2 * D_INNER + n * (2 * D_STATE + 1);

        if (tid < D_STATE) {
            float dtr = bc[2 * D_STATE] + dtb;
            float dt  = fmaxf(dtr, 0.f) + log1pf(expf(-fabsf(dtr)));
            sA[buf][tid] = expf(s_negA[tid] * dt);
            sB[buf][tid] = bc[tid] * dt;
            sC[buf][tid] = bc[D_STATE + tid];
        }
        const float xv = xconv[tok * D_INNER + n * HEADDIM + d];
        __syncthreads();

        float accv = 0.f;
        #pragma unroll
        for (int j4 = 0; j4 < 4; j4++) {
            float4 a4 = *reinterpret_cast<const float4*>(&sA[buf][s0 + j4 * 4]);
            float4 b4 = *reinterpret_cast<const float4*>(&sB[buf][s0 + j4 * 4]);
            float4 c4 = *reinterpret_cast<const float4*>(&sC[buf][s0 + j4 * 4]);
            h[j4*4+0] = fmaf(a4.x, h[j4*4+0], b4.x * xv);
            h[j4*4+1] = fmaf(a4.y, h[j4*4+1], b4.y * xv);
            h[j4*4+2] = fmaf(a4.z, h[j4*4+2], b4.z * xv);
            h[j4*4+3] = fmaf(a4.w, h[j4*4+3], b4.w * xv);
            accv = fmaf(c4.x, h[j4*4+0], accv);
            accv = fmaf(c4.y, h[j4*4+1], accv);
            accv = fmaf(c4.z, h[j4*4+2], accv);
            accv = fmaf(c4.w, h[j4*4+3], accv);
        }
        accv += __shfl_xor_sync(0xFFFFFFFFu, accv, 1);
        accv += __shfl_xor_sync(0xFFFFFFFFu, accv, 2);

        if (q == 0) {
            float yv = fmaf(Dn, xv, accv);
            float zv = row[D_INNER + n * HEADDIM + d];
            float sz = zv / (1.f + expf(-zv));
            float o  = yv * sz;
            __nv_bfloat16 oh = __float2bfloat16(o);
            size_t oi = tok * D_INNER + n * HEADDIM + d;
            y_hi[oi] = oh;
            y_lo[oi] = __float2bfloat16(o - __bfloat162float(oh));
        }
        buf ^= 1;
    }
}

// ---------------- launcher ---------------------------------------------------
extern "C" void kernel_launch(void* const* d_in, const int* in_sizes, int n_in,
                              void* d_out, int out_size)
{
    const float* x       = (const float*)d_in[0];
    const float* W_in    = (const float*)d_in[1];
    const float* conv_w  = (const float*)d_in[2];
    const float* conv_b  = (const float*)d_in[3];
    const float* A_log   = (const float*)d_in[4];
    const float* Dp      = (const float*)d_in[5];
    const float* dt_bias = (const float*)d_in[6];
    const float* W_out   = (const float*)d_in[7];
    float* out = (float*)d_out;

    float *proj, *xconv;
    __nv_bfloat16 *xh, *xl, *wih, *wil, *woh, *wol, *yh, *yl;
    cudaGetSymbolAddress((void**)&proj,  g_proj);
    cudaGetSymbolAddress((void**)&xconv, g_xconv);
    cudaGetSymbolAddress((void**)&xh,  g_x_hi);    cudaGetSymbolAddress((void**)&xl,  g_x_lo);
    cudaGetSymbolAddress((void**)&wih, g_Win_hi);  cudaGetSymbolAddress((void**)&wil, g_Win_lo);
    cudaGetSymbolAddress((void**)&woh, g_Wout_hi); cudaGetSymbolAddress((void**)&wol, g_Wout_lo);
    cudaGetSymbolAddress((void**)&yh,  g_y_hi);    cudaGetSymbolAddress((void**)&yl,  g_y_lo);

    cudaFuncSetAttribute(gemm_mma, cudaFuncAttributeMaxDynamicSharedMemorySize, GEMM_SMEM);

    // 0) fp32 -> bf16 hi/lo splits (W_in zero-padded to 8320 rows)
    {
        int nx = NTOK * D_MODEL;
        split_bf16<<<(nx + 255) / 256, 256>>>(x, xh, xl, nx, nx);
        int nwi = D_PROJ * D_MODEL, nwp = NPROJ_PAD * D_MODEL;
        split_bf16<<<(nwp + 255) / 256, 256>>>(W_in, wih, wil, nwi, nwp);
        int nwo = D_MODEL * D_INNER;
        split_bf16<<<(nwo + 255) / 256, 256>>>(W_out, woh, wol, nwo, nwo);
    }
    // 1) proj = x @ W_in^T
    {
        dim3 grid(NPROJ_PAD / 128, NTOK / 128);
        gemm_mma<<<grid, 256, GEMM_SMEM>>>(xh, xl, wih, wil, proj, NTOK, D_PROJ, D_MODEL);
    }
    // 2) conv + silu
    {
        int total = NTOK * D_INNER;
        conv_silu_kernel<<<(total + 255) / 256, 256>>>(proj, conv_w, conv_b, xconv);
    }
    // 3) selective scan + skip + gate (emits y as bf16 hi/lo)
    {
        ssm_scan_kernel<<<2 * BATCH * NHEADS, 128>>>(proj, xconv, A_log, Dp, dt_bias, yh, yl);
    }
    // 4) out = y @ W_out^T
    {
        dim3 grid(D_MODEL / 128, NTOK / 128);
        gemm_mma<<<grid, 256, GEMM_SMEM>>>(yh, yl, woh, wol, out, NTOK, D_MODEL, D_INNER);
    }
}

// round 10
// speedup vs baseline: 2.0880x; 1.7918x over previous
#include <cuda_runtime.h>
#include <cuda_bf16.h>
#include <math.h>
#include <stdint.h>

#define D_MODEL   1024
#define D_STATE   64
#define D_CONV    4
#define D_INNER   2048
#define NHEADS    32
#define HEADDIM   64
#define D_PROJ    8224
#define BATCH     2
#define SEQLEN    1024
#define NTOK      (BATCH*SEQLEN)     // 2048
#define NPROJ_PAD 8320               // D_PROJ padded to 65*128

// ---------------- scratch (static device allocations) ----------------------
__device__ float g_proj [(size_t)NTOK * D_PROJ];
__device__ float g_xconv[(size_t)NTOK * D_INNER];
__device__ __nv_bfloat16 g_x_hi  [(size_t)NTOK * D_MODEL];
__device__ __nv_bfloat16 g_x_lo  [(size_t)NTOK * D_MODEL];
__device__ __nv_bfloat16 g_Win_hi[(size_t)NPROJ_PAD * D_MODEL];
__device__ __nv_bfloat16 g_Win_lo[(size_t)NPROJ_PAD * D_MODEL];
__device__ __nv_bfloat16 g_Wout_hi[(size_t)D_MODEL * D_INNER];
__device__ __nv_bfloat16 g_Wout_lo[(size_t)D_MODEL * D_INNER];
__device__ __nv_bfloat16 g_y_hi  [(size_t)NTOK * D_INNER];
__device__ __nv_bfloat16 g_y_lo  [(size_t)NTOK * D_INNER];

// ---------------- helpers ---------------------------------------------------
__device__ __forceinline__ uint32_t smem_u32(const void* p) {
    uint32_t a;
    asm("{ .reg .u64 t; cvta.to.shared.u64 t, %1; cvt.u32.u64 %0, t; }" : "=r"(a) : "l"(p));
    return a;
}
#define CP_ASYNC16(dst, src) \
    asm volatile("cp.async.cg.shared.global [%0], [%1], 16;" :: "r"(dst), "l"(src) : "memory")
#define CP_COMMIT() asm volatile("cp.async.commit_group;" ::: "memory")

__device__ __forceinline__ void ldmatrix_x4(uint32_t* r, uint32_t addr) {
    asm volatile("ldmatrix.sync.aligned.m8n8.x4.shared.b16 {%0,%1,%2,%3}, [%4];"
        : "=r"(r[0]), "=r"(r[1]), "=r"(r[2]), "=r"(r[3]) : "r"(addr));
}
__device__ __forceinline__ void mma16816(float* c, const uint32_t* a, const uint32_t* b) {
    asm volatile("mma.sync.aligned.m16n8k16.row.col.f32.bf16.bf16.f32 "
        "{%0,%1,%2,%3}, {%4,%5,%6,%7}, {%8,%9}, {%0,%1,%2,%3};"
        : "+f"(c[0]), "+f"(c[1]), "+f"(c[2]), "+f"(c[3])
        : "r"(a[0]), "r"(a[1]), "r"(a[2]), "r"(a[3]), "r"(b[0]), "r"(b[1]));
}

// ---------------- fp32 -> bf16 hi/lo split ----------------------------------
__global__ void split_bf16(const float* __restrict__ in, __nv_bfloat16* __restrict__ hi,
                           __nv_bfloat16* __restrict__ lo, int n_in, int n_tot)
{
    int i = blockIdx.x * blockDim.x + threadIdx.x;
    if (i >= n_tot) return;
    float v = (i < n_in) ? in[i] : 0.f;
    __nv_bfloat16 h = __float2bfloat16(v);
    hi[i] = h;
    lo[i] = __float2bfloat16(v - __bfloat162float(h));
}

// ---------------- split-bf16 tensor-core GEMM (NT) via mma.sync --------------
#define ROWB    80
#define TILE_B  (128 * ROWB)          // 10240
#define STAGE_B (4 * TILE_B)          // Ah, Al, Bh, Bl
#define GEMM_SMEM (2 * STAGE_B)       // 81920

__global__ __launch_bounds__(256, 2)
void gemm_mma(const __nv_bfloat16* __restrict__ Ah, const __nv_bfloat16* __restrict__ Al,
              const __nv_bfloat16* __restrict__ Bh, const __nv_bfloat16* __restrict__ Bl,
              float* __restrict__ C, int M, int N, int K)
{
    extern __shared__ char smem[];
    const uint32_t sb = smem_u32(smem);
    const int tid  = threadIdx.x;
    const int lane = tid & 31;
    const int wid  = tid >> 5;
    const int wm   = wid & 3;
    const int wn   = wid >> 2;

    const int m0 = blockIdx.y * 128;
    const int n0 = blockIdx.x * 128;
    const int T  = K / 32;

    const __nv_bfloat16* gsrc[4] = {Ah, Al, Bh, Bl};
    const int grow[4] = {m0, m0, n0, n0};

    const int lr = tid >> 2;
    const int lc = tid & 3;
    auto load_stage = [&](int stg, int k0) {
        uint32_t base = sb + stg * STAGE_B;
        #pragma unroll
        for (int ts = 0; ts < 4; ts++) {
            const __nv_bfloat16* g = gsrc[ts] + (size_t)(grow[ts] + lr) * K + k0 + lc * 8;
            uint32_t dst = base + ts * TILE_B + lr * ROWB + lc * 16;
            CP_ASYNC16(dst, g);
            CP_ASYNC16(dst + 64 * ROWB, g + (size_t)64 * K);
        }
    };

    load_stage(0, 0);
    CP_COMMIT();

    float acc[2][8][4];
    #pragma unroll
    for (int i = 0; i < 2; i++)
        #pragma unroll
        for (int j = 0; j < 8; j++)
            #pragma unroll
            for (int k = 0; k < 4; k++) acc[i][j][k] = 0.f;

    const int a_row = wm * 32 + (lane & 15);
    const int a_k   = (lane >> 4) << 3;
    const int b_row = wn * 64 + (lane & 7) + ((lane & 16) >> 1);
    const int b_k   = lane & 8;

    for (int t = 0; t < T; t++) {
        if (t + 1 < T) {
            load_stage((t + 1) & 1, (t + 1) * 32);
            CP_COMMIT();
            asm volatile("cp.async.wait_group 1;" ::: "memory");
        } else {
            asm volatile("cp.async.wait_group 0;" ::: "memory");
        }
        __syncthreads();

        const uint32_t st = sb + (t & 1) * STAGE_B;
        #pragma unroll
        for (int kk = 0; kk < 32; kk += 16) {
            #pragma unroll
            for (int sp = 0; sp < 3; sp++) {
                const uint32_t Ab = st + ((sp == 2) ? TILE_B : 0);
                const uint32_t Bb = st + 2 * TILE_B + ((sp == 1) ? TILE_B : 0);
                uint32_t a[2][4];
                #pragma unroll
                for (int mf = 0; mf < 2; mf++)
                    ldmatrix_x4(a[mf], Ab + (a_row + mf * 16) * ROWB + (kk + a_k) * 2);
                uint32_t b[8][2];
                #pragma unroll
                for (int nb = 0; nb < 4; nb++) {
                    uint32_t r[4];
                    ldmatrix_x4(r, Bb + (b_row + nb * 16) * ROWB + (kk + b_k) * 2);
                    b[nb * 2][0] = r[0]; b[nb * 2][1] = r[1];
                    b[nb * 2 + 1][0] = r[2]; b[nb * 2 + 1][1] = r[3];
                }
                #pragma unroll
                for (int mf = 0; mf < 2; mf++)
                    #pragma unroll
                    for (int nf = 0; nf < 8; nf++)
                        mma16816(acc[mf][nf], a[mf], b[nf]);
            }
        }
        __syncthreads();
    }

    #pragma unroll
    for (int mf = 0; mf < 2; mf++) {
        const int r0 = m0 + wm * 32 + mf * 16 + (lane >> 2);
        #pragma unroll
        for (int nf = 0; nf < 8; nf++) {
            const int col = n0 + wn * 64 + nf * 8 + (lane & 3) * 2;
            if (col < N) {
                float2 v0 = make_float2(acc[mf][nf][0], acc[mf][nf][1]);
                float2 v1 = make_float2(acc[mf][nf][2], acc[mf][nf][3]);
                *reinterpret_cast<float2*>(&C[(size_t)r0 * N + col]) = v0;
                *reinterpret_cast<float2*>(&C[(size_t)(r0 + 8) * N + col]) = v1;
            }
        }
    }
}

// ---------------- depthwise causal conv(4) + bias + SiLU ---------------------
__global__ void conv_silu_kernel(const float* __restrict__ proj,
                                 const float* __restrict__ conv_w,
                                 const float* __restrict__ conv_b,
                                 float* __restrict__ xconv)
{
    int idx = blockIdx.x * blockDim.x + threadIdx.x;
    if (idx >= NTOK * D_INNER) return;
    int c   = idx % D_INNER;
    int tok = idx / D_INNER;
    int b   = tok / SEQLEN;
    int t   = tok % SEQLEN;

    float acc = conv_b[c];
    #pragma unroll
    for (int j = 0; j < D_CONV; j++) {
        int tt = t - (D_CONV - 1) + j;
        if (tt >= 0)
            acc = fmaf(conv_w[c * D_CONV + j],
                       proj[(size_t)(b * SEQLEN + tt) * D_PROJ + c], acc);
    }
    float sig = 1.f / (1.f + expf(-acc));
    xconv[idx] = acc * sig;
}

// ---------------- selective scan (software-pipelined) ------------------------
// 128 blocks = (bh, d-half). 128 threads: dl = tid>>2 (32 d lanes), q = tid&3
// owns 16 states. Depth-2 register prefetch of all global operands; coefficient
// compute for step t+1 overlapped with the h-update of step t (alternate shared
// buffer); one __syncthreads per step.
__global__ __launch_bounds__(128)
void ssm_scan_kernel(const float* __restrict__ proj,
                     const float* __restrict__ xconv,
                     const float* __restrict__ A_log,
                     const float* __restrict__ Dp,
                     const float* __restrict__ dt_bias,
                     __nv_bfloat16* __restrict__ y_hi,
                     __nv_bfloat16* __restrict__ y_lo)
{
    const int bh2 = blockIdx.x;           // 0..127
    const int bh  = bh2 >> 1;
    const int dg  = bh2 & 1;
    const int b   = bh / NHEADS;
    const int n   = bh % NHEADS;
    const int tid = threadIdx.x;
    const int dl  = tid >> 2;
    const int q   = tid & 3;
    const int d   = dg * 32 + dl;

    __shared__ float sA[2][D_STATE];
    __shared__ float sB[2][D_STATE];
    __shared__ float sC[2][D_STATE];

    float negA = 0.f;
    if (tid < D_STATE) negA = -expf(A_log[n * D_STATE + tid]);

    const float Dn  = Dp[n];
    const float dtb = dt_bias[n];

    const float* projB = proj + (size_t)b * SEQLEN * D_PROJ;
    const float* bcB   = projB + 2 * D_INNER + n * (2 * D_STATE + 1);
    const float* zB    = projB + D_INNER + n * HEADDIM + d;
    const float* xB    = xconv + (size_t)b * SEQLEN * D_INNER + n * HEADDIM + d;

    // depth-2 prefetch registers: slot s holds step-t data with t&1 == s
    float pB[2], pC[2], pDt[2], pX[2], pZ[2];

    {   // prologue: load steps 0 and 1
        #pragma unroll
        for (int s = 0; s < 2; s++) {
            if (tid < D_STATE) {
                const float* bc = bcB + (size_t)s * D_PROJ;
                pB[s]  = bc[tid];
                pC[s]  = bc[D_STATE + tid];
                pDt[s] = bc[2 * D_STATE];
            }
            pX[s] = xB[(size_t)s * D_INNER];
            pZ[s] = zB[(size_t)s * D_PROJ];
        }
        // coefficients for step 0 -> buffer 0
        if (tid < D_STATE) {
            float dtr = pDt[0] + dtb;
            float dt  = fmaxf(dtr, 0.f) + log1pf(expf(-fabsf(dtr)));
            sA[0][tid] = expf(negA * dt);
            sB[0][tid] = pB[0] * dt;
            sC[0][tid] = pC[0];
        }
    }
    __syncthreads();

    float h[16];
    #pragma unroll
    for (int i = 0; i < 16; i++) h[i] = 0.f;

    const int s0 = q * 16;
    int buf = 0;

    #pragma unroll 2
    for (int t = 0; t < SEQLEN; t++) {
        const int slot  = t & 1;       // holds step t operands
        const int nslot = slot ^ 1;    // holds step t+1 operands

        const float xv = pX[slot];
        const float zv = pZ[slot];

        // coefficients for step t+1 -> alternate buffer (no race with reads of buf)
        if (t + 1 < SEQLEN && tid < D_STATE) {
            float dtr = pDt[nslot] + dtb;
            float dt  = fmaxf(dtr, 0.f) + log1pf(expf(-fabsf(dtr)));
            sA[buf ^ 1][tid] = expf(negA * dt);
            sB[buf ^ 1][tid] = pB[nslot] * dt;
            sC[buf ^ 1][tid] = pC[nslot];
        }

        // prefetch step t+2 into slot (t+2)&1 == slot (xv/zv already consumed)
        if (t + 2 < SEQLEN) {
            const int tp = t + 2;
            if (tid < D_STATE) {
                const float* bc = bcB + (size_t)tp * D_PROJ;
                pB[slot]  = bc[tid];
                pC[slot]  = bc[D_STATE + tid];
                pDt[slot] = bc[2 * D_STATE];
            }
            pX[slot] = xB[(size_t)tp * D_INNER];
            pZ[slot] = zB[(size_t)tp * D_PROJ];
        }

        // h update + C-contraction for step t (4 split accumulators)
        float a0 = 0.f, a1 = 0.f, a2 = 0.f, a3 = 0.f;
        #pragma unroll
        for (int j4 = 0; j4 < 4; j4++) {
            float4 a4 = *reinterpret_cast<const float4*>(&sA[buf][s0 + j4 * 4]);
            float4 b4 = *reinterpret_cast<const float4*>(&sB[buf][s0 + j4 * 4]);
            float4 c4 = *reinterpret_cast<const float4*>(&sC[buf][s0 + j4 * 4]);
            h[j4*4+0] = fmaf(a4.x, h[j4*4+0], b4.x * xv);
            h[j4*4+1] = fmaf(a4.y, h[j4*4+1], b4.y * xv);
            h[j4*4+2] = fmaf(a4.z, h[j4*4+2], b4.z * xv);
            h[j4*4+3] = fmaf(a4.w, h[j4*4+3], b4.w * xv);
            a0 = fmaf(c4.x, h[j4*4+0], a0);
            a1 = fmaf(c4.y, h[j4*4+1], a1);
            a2 = fmaf(c4.z, h[j4*4+2], a2);
            a3 = fmaf(c4.w, h[j4*4+3], a3);
        }
        float accv = (a0 + a1) + (a2 + a3);
        accv += __shfl_xor_sync(0xFFFFFFFFu, accv, 1);
        accv += __shfl_xor_sync(0xFFFFFFFFu, accv, 2);

        if (q == 0) {
            float yv = fmaf(Dn, xv, accv);
            float sz = zv / (1.f + expf(-zv));
            float o  = yv * sz;
            __nv_bfloat16 oh = __float2bfloat16(o);
            size_t oi = (size_t)(b * SEQLEN + t) * D_INNER + n * HEADDIM + d;
            y_hi[oi] = oh;
            y_lo[oi] = __float2bfloat16(o - __bfloat162float(oh));
        }
        __syncthreads();
        buf ^= 1;
    }
}

// ---------------- launcher ---------------------------------------------------
extern "C" void kernel_launch(void* const* d_in, const int* in_sizes, int n_in,
                              void* d_out, int out_size)
{
    const float* x       = (const float*)d_in[0];
    const float* W_in    = (const float*)d_in[1];
    const float* conv_w  = (const float*)d_in[2];
    const float* conv_b  = (const float*)d_in[3];
    const float* A_log   = (const float*)d_in[4];
    const float* Dp      = (const float*)d_in[5];
    const float* dt_bias = (const float*)d_in[6];
    const float* W_out   = (const float*)d_in[7];
    float* out = (float*)d_out;

    float *proj, *xconv;
    __nv_bfloat16 *xh, *xl, *wih, *wil, *woh, *wol, *yh, *yl;
    cudaGetSymbolAddress((void**)&proj,  g_proj);
    cudaGetSymbolAddress((void**)&xconv, g_xconv);
    cudaGetSymbolAddress((void**)&xh,  g_x_hi);    cudaGetSymbolAddress((void**)&xl,  g_x_lo);
    cudaGetSymbolAddress((void**)&wih, g_Win_hi);  cudaGetSymbolAddress((void**)&wil, g_Win_lo);
    cudaGetSymbolAddress((void**)&woh, g_Wout_hi); cudaGetSymbolAddress((void**)&wol, g_Wout_lo);
    cudaGetSymbolAddress((void**)&yh,  g_y_hi);    cudaGetSymbolAddress((void**)&yl,  g_y_lo);

    cudaFuncSetAttribute(gemm_mma, cudaFuncAttributeMaxDynamicSharedMemorySize, GEMM_SMEM);

    // 0) fp32 -> bf16 hi/lo splits (W_in zero-padded to 8320 rows)
    {
        int nx = NTOK * D_MODEL;
        split_bf16<<<(nx + 255) / 256, 256>>>(x, xh, xl, nx, nx);
        int nwi = D_PROJ * D_MODEL, nwp = NPROJ_PAD * D_MODEL;
        split_bf16<<<(nwp + 255) / 256, 256>>>(W_in, wih, wil, nwi, nwp);
        int nwo = D_MODEL * D_INNER;
        split_bf16<<<(nwo + 255) / 256, 256>>>(W_out, woh, wol, nwo, nwo);
    }
    // 1) proj = x @ W_in^T
    {
        dim3 grid(NPROJ_PAD / 128, NTOK / 128);
        gemm_mma<<<grid, 256, GEMM_SMEM>>>(xh, xl, wih, wil, proj, NTOK, D_PROJ, D_MODEL);
    }
    // 2) conv + silu
    {
        int total = NTOK * D_INNER;
        conv_silu_kernel<<<(total + 255) / 256, 256>>>(proj, conv_w, conv_b, xconv);
    }
    // 3) selective scan + skip + gate (emits y as bf16 hi/lo)
    {
        ssm_scan_kernel<<<2 * BATCH * NHEADS, 128>>>(proj, xconv, A_log, Dp, dt_bias, yh, yl);
    }
    // 4) out = y @ W_out^T
    {
        dim3 grid(D_MODEL / 128, NTOK / 128);
        gemm_mma<<<grid, 256, GEMM_SMEM>>>(yh, yl, woh, wol, out, NTOK, D_MODEL, D_INNER);
    }
}

// round 11
// speedup vs baseline: 2.2781x; 1.0911x over previous
#include <cuda_runtime.h>
#include <cuda_bf16.h>
#include <math.h>
#include <stdint.h>

#define D_MODEL   1024
#define D_STATE   64
#define D_CONV    4
#define D_INNER   2048
#define NHEADS    32
#define HEADDIM   64
#define D_PROJ    8224
#define BATCH     2
#define SEQLEN    1024
#define NTOK      (BATCH*SEQLEN)     // 2048
#define NPROJ_PAD 8320               // D_PROJ padded to 65*128

// ---------------- scratch (static device allocations) ----------------------
__device__ float g_proj [(size_t)NTOK * D_PROJ];
__device__ float g_xconv[(size_t)NTOK * D_INNER];
__device__ __nv_bfloat16 g_x_hi  [(size_t)NTOK * D_MODEL];
__device__ __nv_bfloat16 g_x_lo  [(size_t)NTOK * D_MODEL];
__device__ __nv_bfloat16 g_Win_hi[(size_t)NPROJ_PAD * D_MODEL];
__device__ __nv_bfloat16 g_Win_lo[(size_t)NPROJ_PAD * D_MODEL];
__device__ __nv_bfloat16 g_Wout_hi[(size_t)D_MODEL * D_INNER];
__device__ __nv_bfloat16 g_Wout_lo[(size_t)D_MODEL * D_INNER];
__device__ __nv_bfloat16 g_y_hi  [(size_t)NTOK * D_INNER];
__device__ __nv_bfloat16 g_y_lo  [(size_t)NTOK * D_INNER];

// ---------------- helpers ---------------------------------------------------
__device__ __forceinline__ uint32_t smem_u32(const void* p) {
    uint32_t a;
    asm("{ .reg .u64 t; cvta.to.shared.u64 t, %1; cvt.u32.u64 %0, t; }" : "=r"(a) : "l"(p));
    return a;
}
#define CP_ASYNC16(dst, src) \
    asm volatile("cp.async.cg.shared.global [%0], [%1], 16;" :: "r"(dst), "l"(src) : "memory")
#define CP_COMMIT() asm volatile("cp.async.commit_group;" ::: "memory")

__device__ __forceinline__ void ldmatrix_x4(uint32_t* r, uint32_t addr) {
    asm volatile("ldmatrix.sync.aligned.m8n8.x4.shared.b16 {%0,%1,%2,%3}, [%4];"
        : "=r"(r[0]), "=r"(r[1]), "=r"(r[2]), "=r"(r[3]) : "r"(addr));
}
__device__ __forceinline__ void mma16816(float* c, const uint32_t* a, const uint32_t* b) {
    asm volatile("mma.sync.aligned.m16n8k16.row.col.f32.bf16.bf16.f32 "
        "{%0,%1,%2,%3}, {%4,%5,%6,%7}, {%8,%9}, {%0,%1,%2,%3};"
        : "+f"(c[0]), "+f"(c[1]), "+f"(c[2]), "+f"(c[3])
        : "r"(a[0]), "r"(a[1]), "r"(a[2]), "r"(a[3]), "r"(b[0]), "r"(b[1]));
}

// ---------------- fp32 -> bf16 hi/lo split ----------------------------------
__global__ void split_bf16(const float* __restrict__ in, __nv_bfloat16* __restrict__ hi,
                           __nv_bfloat16* __restrict__ lo, int n_in, int n_tot)
{
    int i = blockIdx.x * blockDim.x + threadIdx.x;
    if (i >= n_tot) return;
    float v = (i < n_in) ? in[i] : 0.f;
    __nv_bfloat16 h = __float2bfloat16(v);
    hi[i] = h;
    lo[i] = __float2bfloat16(v - __bfloat162float(h));
}

// ---------------- split-bf16 tensor-core GEMM (NT) via mma.sync --------------
#define ROWB    80
#define TILE_B  (128 * ROWB)          // 10240
#define STAGE_B (4 * TILE_B)          // Ah, Al, Bh, Bl
#define GEMM_SMEM (2 * STAGE_B)       // 81920

__global__ __launch_bounds__(256, 2)
void gemm_mma(const __nv_bfloat16* __restrict__ Ah, const __nv_bfloat16* __restrict__ Al,
              const __nv_bfloat16* __restrict__ Bh, const __nv_bfloat16* __restrict__ Bl,
              float* __restrict__ C, int M, int N, int K)
{
    extern __shared__ char smem[];
    const uint32_t sb = smem_u32(smem);
    const int tid  = threadIdx.x;
    const int lane = tid & 31;
    const int wid  = tid >> 5;
    const int wm   = wid & 3;
    const int wn   = wid >> 2;

    const int m0 = blockIdx.y * 128;
    const int n0 = blockIdx.x * 128;
    const int T  = K / 32;

    const __nv_bfloat16* gsrc[4] = {Ah, Al, Bh, Bl};
    const int grow[4] = {m0, m0, n0, n0};

    const int lr = tid >> 2;
    const int lc = tid & 3;
    auto load_stage = [&](int stg, int k0) {
        uint32_t base = sb + stg * STAGE_B;
        #pragma unroll
        for (int ts = 0; ts < 4; ts++) {
            const __nv_bfloat16* g = gsrc[ts] + (size_t)(grow[ts] + lr) * K + k0 + lc * 8;
            uint32_t dst = base + ts * TILE_B + lr * ROWB + lc * 16;
            CP_ASYNC16(dst, g);
            CP_ASYNC16(dst + 64 * ROWB, g + (size_t)64 * K);
        }
    };

    load_stage(0, 0);
    CP_COMMIT();

    float acc[2][8][4];
    #pragma unroll
    for (int i = 0; i < 2; i++)
        #pragma unroll
        for (int j = 0; j < 8; j++)
            #pragma unroll
            for (int k = 0; k < 4; k++) acc[i][j][k] = 0.f;

    const int a_row = wm * 32 + (lane & 15);
    const int a_k   = (lane >> 4) << 3;
    const int b_row = wn * 64 + (lane & 7) + ((lane & 16) >> 1);
    const int b_k   = lane & 8;

    for (int t = 0; t < T; t++) {
        if (t + 1 < T) {
            load_stage((t + 1) & 1, (t + 1) * 32);
            CP_COMMIT();
            asm volatile("cp.async.wait_group 1;" ::: "memory");
        } else {
            asm volatile("cp.async.wait_group 0;" ::: "memory");
        }
        __syncthreads();

        const uint32_t st = sb + (t & 1) * STAGE_B;
        #pragma unroll
        for (int kk = 0; kk < 32; kk += 16) {
            #pragma unroll
            for (int sp = 0; sp < 3; sp++) {
                const uint32_t Ab = st + ((sp == 2) ? TILE_B : 0);
                const uint32_t Bb = st + 2 * TILE_B + ((sp == 1) ? TILE_B : 0);
                uint32_t a[2][4];
                #pragma unroll
                for (int mf = 0; mf < 2; mf++)
                    ldmatrix_x4(a[mf], Ab + (a_row + mf * 16) * ROWB + (kk + a_k) * 2);
                uint32_t b[8][2];
                #pragma unroll
                for (int nb = 0; nb < 4; nb++) {
                    uint32_t r[4];
                    ldmatrix_x4(r, Bb + (b_row + nb * 16) * ROWB + (kk + b_k) * 2);
                    b[nb * 2][0] = r[0]; b[nb * 2][1] = r[1];
                    b[nb * 2 + 1][0] = r[2]; b[nb * 2 + 1][1] = r[3];
                }
                #pragma unroll
                for (int mf = 0; mf < 2; mf++)
                    #pragma unroll
                    for (int nf = 0; nf < 8; nf++)
                        mma16816(acc[mf][nf], a[mf], b[nf]);
            }
        }
        __syncthreads();
    }

    #pragma unroll
    for (int mf = 0; mf < 2; mf++) {
        const int r0 = m0 + wm * 32 + mf * 16 + (lane >> 2);
        #pragma unroll
        for (int nf = 0; nf < 8; nf++) {
            const int col = n0 + wn * 64 + nf * 8 + (lane & 3) * 2;
            if (col < N) {
                float2 v0 = make_float2(acc[mf][nf][0], acc[mf][nf][1]);
                float2 v1 = make_float2(acc[mf][nf][2], acc[mf][nf][3]);
                *reinterpret_cast<float2*>(&C[(size_t)r0 * N + col]) = v0;
                *reinterpret_cast<float2*>(&C[(size_t)(r0 + 8) * N + col]) = v1;
            }
        }
    }
}

// ---------------- depthwise causal conv(4) + bias + SiLU ---------------------
__global__ void conv_silu_kernel(const float* __restrict__ proj,
                                 const float* __restrict__ conv_w,
                                 const float* __restrict__ conv_b,
                                 float* __restrict__ xconv)
{
    int idx = blockIdx.x * blockDim.x + threadIdx.x;
    if (idx >= NTOK * D_INNER) return;
    int c   = idx % D_INNER;
    int tok = idx / D_INNER;
    int b   = tok / SEQLEN;
    int t   = tok % SEQLEN;

    float acc = conv_b[c];
    #pragma unroll
    for (int j = 0; j < D_CONV; j++) {
        int tt = t - (D_CONV - 1) + j;
        if (tt >= 0)
            acc = fmaf(conv_w[c * D_CONV + j],
                       proj[(size_t)(b * SEQLEN + tt) * D_PROJ + c], acc);
    }
    float sig = 1.f / (1.f + expf(-acc));
    xconv[idx] = acc * sig;
}

// ---------------- selective scan (4-deep software pipeline) ------------------
// 128 blocks = (bh, d-half). 128 threads: dl = tid>>2 (32 d lanes), q = tid&3
// owns 16 states. 4-slot register ring: at step t we consume slot t&3,
// compute t+1 coefficients from slot (t+1)&3 (loaded at t-3 -> 3-step latency
// cover), and prefetch step t+4 into slot t&3. One __syncthreads per step.
__global__ __launch_bounds__(128)
void ssm_scan_kernel(const float* __restrict__ proj,
                     const float* __restrict__ xconv,
                     const float* __restrict__ A_log,
                     const float* __restrict__ Dp,
                     const float* __restrict__ dt_bias,
                     __nv_bfloat16* __restrict__ y_hi,
                     __nv_bfloat16* __restrict__ y_lo)
{
    const int bh2 = blockIdx.x;           // 0..127
    const int bh  = bh2 >> 1;
    const int dg  = bh2 & 1;
    const int b   = bh / NHEADS;
    const int n   = bh % NHEADS;
    const int tid = threadIdx.x;
    const int dl  = tid >> 2;
    const int q   = tid & 3;
    const int d   = dg * 32 + dl;

    __shared__ float sA[2][D_STATE];
    __shared__ float sB[2][D_STATE];
    __shared__ float sC[2][D_STATE];

    float negA = 0.f;
    if (tid < D_STATE) negA = -expf(A_log[n * D_STATE + tid]);

    const float Dn  = Dp[n];
    const float dtb = dt_bias[n];

    const float* projB = proj + (size_t)b * SEQLEN * D_PROJ;
    const float* bcB   = projB + 2 * D_INNER + n * (2 * D_STATE + 1);
    const float* zB    = projB + D_INNER + n * HEADDIM + d;
    const float* xB    = xconv + (size_t)b * SEQLEN * D_INNER + n * HEADDIM + d;

    // 4-slot prefetch ring: slot s holds step-t data with t&3 == s
    float pB[4], pC[4], pDt[4], pX[4], pZ[4];

    {   // prologue: load steps 0..3
        #pragma unroll
        for (int s = 0; s < 4; s++) {
            if (tid < D_STATE) {
                const float* bc = bcB + (size_t)s * D_PROJ;
                pB[s]  = bc[tid];
                pC[s]  = bc[D_STATE + tid];
                pDt[s] = bc[2 * D_STATE];
            }
            pX[s] = xB[(size_t)s * D_INNER];
            pZ[s] = zB[(size_t)s * D_PROJ];
        }
        // coefficients for step 0 -> buffer 0
        if (tid < D_STATE) {
            float dtr = pDt[0] + dtb;
            float dt  = fmaxf(dtr, 0.f) + log1pf(expf(-fabsf(dtr)));
            sA[0][tid] = expf(negA * dt);
            sB[0][tid] = pB[0] * dt;
            sC[0][tid] = pC[0];
        }
    }
    __syncthreads();

    float h[16];
    #pragma unroll
    for (int i = 0; i < 16; i++) h[i] = 0.f;

    const int s0 = q * 16;
    int buf = 0;

    #pragma unroll 4
    for (int t = 0; t < SEQLEN; t++) {
        const int slot  = t & 3;             // operands of step t
        const int nslot = (t + 1) & 3;       // operands of step t+1

        const float xv = pX[slot];
        const float zv = pZ[slot];

        // coefficients for step t+1 -> alternate buffer (operands loaded at t-3)
        if (t + 1 < SEQLEN && tid < D_STATE) {
            float dtr = pDt[nslot] + dtb;
            float dt  = fmaxf(dtr, 0.f) + log1pf(expf(-fabsf(dtr)));
            sA[buf ^ 1][tid] = expf(negA * dt);
            sB[buf ^ 1][tid] = pB[nslot] * dt;
            sC[buf ^ 1][tid] = pC[nslot];
        }

        // prefetch step t+4 into slot (t+4)&3 == slot (its data is consumed)
        if (t + 4 < SEQLEN) {
            const int tp = t + 4;
            if (tid < D_STATE) {
                const float* bc = bcB + (size_t)tp * D_PROJ;
                pB[slot]  = bc[tid];
                pC[slot]  = bc[D_STATE + tid];
                pDt[slot] = bc[2 * D_STATE];
            }
            pX[slot] = xB[(size_t)tp * D_INNER];
            pZ[slot] = zB[(size_t)tp * D_PROJ];
        }

        // h update + C-contraction for step t (4 split accumulators)
        float a0 = 0.f, a1 = 0.f, a2 = 0.f, a3 = 0.f;
        #pragma unroll
        for (int j4 = 0; j4 < 4; j4++) {
            float4 a4 = *reinterpret_cast<const float4*>(&sA[buf][s0 + j4 * 4]);
            float4 b4 = *reinterpret_cast<const float4*>(&sB[buf][s0 + j4 * 4]);
            float4 c4 = *reinterpret_cast<const float4*>(&sC[buf][s0 + j4 * 4]);
            h[j4*4+0] = fmaf(a4.x, h[j4*4+0], b4.x * xv);
            h[j4*4+1] = fmaf(a4.y, h[j4*4+1], b4.y * xv);
            h[j4*4+2] = fmaf(a4.z, h[j4*4+2], b4.z * xv);
            h[j4*4+3] = fmaf(a4.w, h[j4*4+3], b4.w * xv);
            a0 = fmaf(c4.x, h[j4*4+0], a0);
            a1 = fmaf(c4.y, h[j4*4+1], a1);
            a2 = fmaf(c4.z, h[j4*4+2], a2);
            a3 = fmaf(c4.w, h[j4*4+3], a3);
        }
        float accv = (a0 + a1) + (a2 + a3);
        accv += __shfl_xor_sync(0xFFFFFFFFu, accv, 1);
        accv += __shfl_xor_sync(0xFFFFFFFFu, accv, 2);

        if (q == 0) {
            float yv = fmaf(Dn, xv, accv);
            float sz = zv / (1.f + expf(-zv));
            float o  = yv * sz;
            __nv_bfloat16 oh = __float2bfloat16(o);
            size_t oi = (size_t)(b * SEQLEN + t) * D_INNER + n * HEADDIM + d;
            y_hi[oi] = oh;
            y_lo[oi] = __float2bfloat16(o - __bfloat162float(oh));
        }
        __syncthreads();
        buf ^= 1;
    }
}

// ---------------- launcher ---------------------------------------------------
extern "C" void kernel_launch(void* const* d_in, const int* in_sizes, int n_in,
                              void* d_out, int out_size)
{
    const float* x       = (const float*)d_in[0];
    const float* W_in    = (const float*)d_in[1];
    const float* conv_w  = (const float*)d_in[2];
    const float* conv_b  = (const float*)d_in[3];
    const float* A_log   = (const float*)d_in[4];
    const float* Dp      = (const float*)d_in[5];
    const float* dt_bias = (const float*)d_in[6];
    const float* W_out   = (const float*)d_in[7];
    float* out = (float*)d_out;

    float *proj, *xconv;
    __nv_bfloat16 *xh, *xl, *wih, *wil, *woh, *wol, *yh, *yl;
    cudaGetSymbolAddress((void**)&proj,  g_proj);
    cudaGetSymbolAddress((void**)&xconv, g_xconv);
    cudaGetSymbolAddress((void**)&xh,  g_x_hi);    cudaGetSymbolAddress((void**)&xl,  g_x_lo);
    cudaGetSymbolAddress((void**)&wih, g_Win_hi);  cudaGetSymbolAddress((void**)&wil, g_Win_lo);
    cudaGetSymbolAddress((void**)&woh, g_Wout_hi); cudaGetSymbolAddress((void**)&wol, g_Wout_lo);
    cudaGetSymbolAddress((void**)&yh,  g_y_hi);    cudaGetSymbolAddress((void**)&yl,  g_y_lo);

    cudaFuncSetAttribute(gemm_mma, cudaFuncAttributeMaxDynamicSharedMemorySize, GEMM_SMEM);

    // 0) fp32 -> bf16 hi/lo splits (W_in zero-padded to 8320 rows)
    {
        int nx = NTOK * D_MODEL;
        split_bf16<<<(nx + 255) / 256, 256>>>(x, xh, xl, nx, nx);
        int nwi = D_PROJ * D_MODEL, nwp = NPROJ_PAD * D_MODEL;
        split_bf16<<<(nwp + 255) / 256, 256>>>(W_in, wih, wil, nwi, nwp);
        int nwo = D_MODEL * D_INNER;
        split_bf16<<<(nwo + 255) / 256, 256>>>(W_out, woh, wol, nwo, nwo);
    }
    // 1) proj = x @ W_in^T
    {
        dim3 grid(NPROJ_PAD / 128, NTOK / 128);
        gemm_mma<<<grid, 256, GEMM_SMEM>>>(xh, xl, wih, wil, proj, NTOK, D_PROJ, D_MODEL);
    }
    // 2) conv + silu
    {
        int total = NTOK * D_INNER;
        conv_silu_kernel<<<(total + 255) / 256, 256>>>(proj, conv_w, conv_b, xconv);
    }
    // 3) selective scan + skip + gate (emits y as bf16 hi/lo)
    {
        ssm_scan_kernel<<<2 * BATCH * NHEADS, 128>>>(proj, xconv, A_log, Dp, dt_bias, yh, yl);
    }
    // 4) out = y @ W_out^T
    {
        dim3 grid(D_MODEL / 128, NTOK / 128);
        gemm_mma<<<grid, 256, GEMM_SMEM>>>(yh, yl, woh, wol, out, NTOK, D_MODEL, D_INNER);
    }
}

// round 13
// speedup vs baseline: 2.9250x; 1.2840x over previous
#include <cuda_runtime.h>
#include <cuda_bf16.h>
#include <math.h>
#include <stdint.h>

#define D_MODEL   1024
#define D_STATE   64
#define D_CONV    4
#define D_INNER   2048
#define NHEADS    32
#define HEADDIM   64
#define D_PROJ    8224
#define BATCH     2
#define SEQLEN    1024
#define NTOK      (BATCH*SEQLEN)     // 2048
#define NPROJ_PAD 8320               // D_PROJ padded to 65*128
#define NBH       (BATCH*NHEADS)     // 64
#define NSEG      16
#define LSEG      64                 // SEQLEN / NSEG

// ---------------- scratch (static device allocations) ----------------------
__device__ float g_proj [(size_t)NTOK * D_PROJ];
__device__ float g_xconv[(size_t)NTOK * D_INNER];
__device__ __nv_bfloat16 g_x_hi  [(size_t)NTOK * D_MODEL];
__device__ __nv_bfloat16 g_x_lo  [(size_t)NTOK * D_MODEL];
__device__ __nv_bfloat16 g_Win_hi[(size_t)NPROJ_PAD * D_MODEL];
__device__ __nv_bfloat16 g_Win_lo[(size_t)NPROJ_PAD * D_MODEL];
__device__ __nv_bfloat16 g_Wout_hi[(size_t)D_MODEL * D_INNER];
__device__ __nv_bfloat16 g_Wout_lo[(size_t)D_MODEL * D_INNER];
__device__ __nv_bfloat16 g_y_hi  [(size_t)NTOK * D_INNER];
__device__ __nv_bfloat16 g_y_lo  [(size_t)NTOK * D_INNER];
// segmented-scan scratch
__device__ float g_ypart [(size_t)NBH * SEQLEN * HEADDIM];          // C.h_local
__device__ float g_decay [(size_t)NBH * SEQLEN * D_STATE];          // cumprod dA
__device__ float g_hseg  [(size_t)NBH * NSEG * D_STATE * HEADDIM];  // zero-init final states
__device__ float g_hstart[(size_t)NBH * NSEG * D_STATE * HEADDIM];  // true segment-start states
__device__ float g_aprod [(size_t)NBH * NSEG * D_STATE];            // per-segment decay product

// ---------------- helpers ---------------------------------------------------
__device__ __forceinline__ uint32_t smem_u32(const void* p) {
    uint32_t a;
    asm("{ .reg .u64 t; cvta.to.shared.u64 t, %1; cvt.u32.u64 %0, t; }" : "=r"(a) : "l"(p));
    return a;
}
#define CP_ASYNC16(dst, src) \
    asm volatile("cp.async.cg.shared.global [%0], [%1], 16;" :: "r"(dst), "l"(src) : "memory")
#define CP_COMMIT() asm volatile("cp.async.commit_group;" ::: "memory")

__device__ __forceinline__ void ldmatrix_x4(uint32_t* r, uint32_t addr) {
    asm volatile("ldmatrix.sync.aligned.m8n8.x4.shared.b16 {%0,%1,%2,%3}, [%4];"
        : "=r"(r[0]), "=r"(r[1]), "=r"(r[2]), "=r"(r[3]) : "r"(addr));
}
__device__ __forceinline__ void mma16816(float* c, const uint32_t* a, const uint32_t* b) {
    asm volatile("mma.sync.aligned.m16n8k16.row.col.f32.bf16.bf16.f32 "
        "{%0,%1,%2,%3}, {%4,%5,%6,%7}, {%8,%9}, {%0,%1,%2,%3};"
        : "+f"(c[0]), "+f"(c[1]), "+f"(c[2]), "+f"(c[3])
        : "r"(a[0]), "r"(a[1]), "r"(a[2]), "r"(a[3]), "r"(b[0]), "r"(b[1]));
}

// ---------------- fp32 -> bf16 hi/lo split ----------------------------------
__global__ void split_bf16(const float* __restrict__ in, __nv_bfloat16* __restrict__ hi,
                           __nv_bfloat16* __restrict__ lo, int n_in, int n_tot)
{
    int i = blockIdx.x * blockDim.x + threadIdx.x;
    if (i >= n_tot) return;
    float v = (i < n_in) ? in[i] : 0.f;
    __nv_bfloat16 h = __float2bfloat16(v);
    hi[i] = h;
    lo[i] = __float2bfloat16(v - __bfloat162float(h));
}

// ---------------- split-bf16 tensor-core GEMM (NT) via mma.sync --------------
#define ROWB    80
#define TILE_B  (128 * ROWB)
#define STAGE_B (4 * TILE_B)
#define GEMM_SMEM (2 * STAGE_B)

__global__ __launch_bounds__(256, 2)
void gemm_mma(const __nv_bfloat16* __restrict__ Ah, const __nv_bfloat16* __restrict__ Al,
              const __nv_bfloat16* __restrict__ Bh, const __nv_bfloat16* __restrict__ Bl,
              float* __restrict__ C, int M, int N, int K)
{
    extern __shared__ char smem[];
    const uint32_t sb = smem_u32(smem);
    const int tid  = threadIdx.x;
    const int lane = tid & 31;
    const int wid  = tid >> 5;
    const int wm   = wid & 3;
    const int wn   = wid >> 2;

    const int m0 = blockIdx.y * 128;
    const int n0 = blockIdx.x * 128;
    const int T  = K / 32;

    const __nv_bfloat16* gsrc[4] = {Ah, Al, Bh, Bl};
    const int grow[4] = {m0, m0, n0, n0};

    const int lr = tid >> 2;
    const int lc = tid & 3;
    auto load_stage = [&](int stg, int k0) {
        uint32_t base = sb + stg * STAGE_B;
        #pragma unroll
        for (int ts = 0; ts < 4; ts++) {
            const __nv_bfloat16* g = gsrc[ts] + (size_t)(grow[ts] + lr) * K + k0 + lc * 8;
            uint32_t dst = base + ts * TILE_B + lr * ROWB + lc * 16;
            CP_ASYNC16(dst, g);
            CP_ASYNC16(dst + 64 * ROWB, g + (size_t)64 * K);
        }
    };

    load_stage(0, 0);
    CP_COMMIT();

    float acc[2][8][4];
    #pragma unroll
    for (int i = 0; i < 2; i++)
        #pragma unroll
        for (int j = 0; j < 8; j++)
            #pragma unroll
            for (int k = 0; k < 4; k++) acc[i][j][k] = 0.f;

    const int a_row = wm * 32 + (lane & 15);
    const int a_k   = (lane >> 4) << 3;
    const int b_row = wn * 64 + (lane & 7) + ((lane & 16) >> 1);
    const int b_k   = lane & 8;

    for (int t = 0; t < T; t++) {
        if (t + 1 < T) {
            load_stage((t + 1) & 1, (t + 1) * 32);
            CP_COMMIT();
            asm volatile("cp.async.wait_group 1;" ::: "memory");
        } else {
            asm volatile("cp.async.wait_group 0;" ::: "memory");
        }
        __syncthreads();

        const uint32_t st = sb + (t & 1) * STAGE_B;
        #pragma unroll
        for (int kk = 0; kk < 32; kk += 16) {
            #pragma unroll
            for (int sp = 0; sp < 3; sp++) {
                const uint32_t Ab = st + ((sp == 2) ? TILE_B : 0);
                const uint32_t Bb = st + 2 * TILE_B + ((sp == 1) ? TILE_B : 0);
                uint32_t a[2][4];
                #pragma unroll
                for (int mf = 0; mf < 2; mf++)
                    ldmatrix_x4(a[mf], Ab + (a_row + mf * 16) * ROWB + (kk + a_k) * 2);
                uint32_t b[8][2];
                #pragma unroll
                for (int nb = 0; nb < 4; nb++) {
                    uint32_t r[4];
                    ldmatrix_x4(r, Bb + (b_row + nb * 16) * ROWB + (kk + b_k) * 2);
                    b[nb * 2][0] = r[0]; b[nb * 2][1] = r[1];
                    b[nb * 2 + 1][0] = r[2]; b[nb * 2 + 1][1] = r[3];
                }
                #pragma unroll
                for (int mf = 0; mf < 2; mf++)
                    #pragma unroll
                    for (int nf = 0; nf < 8; nf++)
                        mma16816(acc[mf][nf], a[mf], b[nf]);
            }
        }
        __syncthreads();
    }

    #pragma unroll
    for (int mf = 0; mf < 2; mf++) {
        const int r0 = m0 + wm * 32 + mf * 16 + (lane >> 2);
        #pragma unroll
        for (int nf = 0; nf < 8; nf++) {
            const int col = n0 + wn * 64 + nf * 8 + (lane & 3) * 2;
            if (col < N) {
                float2 v0 = make_float2(acc[mf][nf][0], acc[mf][nf][1]);
                float2 v1 = make_float2(acc[mf][nf][2], acc[mf][nf][3]);
                *reinterpret_cast<float2*>(&C[(size_t)r0 * N + col]) = v0;
                *reinterpret_cast<float2*>(&C[(size_t)(r0 + 8) * N + col]) = v1;
            }
        }
    }
}

// ---------------- depthwise causal conv(4) + bias + SiLU ---------------------
__global__ void conv_silu_kernel(const float* __restrict__ proj,
                                 const float* __restrict__ conv_w,
                                 const float* __restrict__ conv_b,
                                 float* __restrict__ xconv)
{
    int idx = blockIdx.x * blockDim.x + threadIdx.x;
    if (idx >= NTOK * D_INNER) return;
    int c   = idx % D_INNER;
    int tok = idx / D_INNER;
    int b   = tok / SEQLEN;
    int t   = tok % SEQLEN;

    float acc = conv_b[c];
    #pragma unroll
    for (int j = 0; j < D_CONV; j++) {
        int tt = t - (D_CONV - 1) + j;
        if (tt >= 0)
            acc = fmaf(conv_w[c * D_CONV + j],
                       proj[(size_t)(b * SEQLEN + tt) * D_PROJ + c], acc);
    }
    float sig = 1.f / (1.f + expf(-acc));
    xconv[idx] = acc * sig;
}

// ---------------- K1: segmented scan (zero-init, 64 steps) -------------------
// grid 2048 = (bh, seg, d-half). 128 threads: dl=tid>>2, q=tid&3 (16 states).
// Emits: y_partial (C.h_local), per-token decay cumprod, final state, decay prod.
__global__ __launch_bounds__(128)
void seg_scan_kernel(const float* __restrict__ proj,
                     const float* __restrict__ xconv,
                     const float* __restrict__ A_log,
                     const float* __restrict__ dt_bias,
                     float* __restrict__ ypart,
                     float* __restrict__ decay,
                     float* __restrict__ hseg,
                     float* __restrict__ aprod)
{
    const int blk = blockIdx.x;           // 0..2047
    const int bh  = blk >> 5;
    const int rem = blk & 31;
    const int seg = rem >> 1;
    const int dg  = rem & 1;
    const int b   = bh / NHEADS;
    const int n   = bh % NHEADS;
    const int tid = threadIdx.x;
    const int dl  = tid >> 2;
    const int q   = tid & 3;
    const int d   = dg * 32 + dl;
    const int t0  = seg * LSEG;

    __shared__ float sA[2][D_STATE];
    __shared__ float sB[2][D_STATE];
    __shared__ float sC[2][D_STATE];

    float negA = 0.f;
    if (tid < D_STATE) negA = -expf(A_log[n * D_STATE + tid]);
    const float dtb = dt_bias[n];

    const float* projB = proj + (size_t)(b * SEQLEN + t0) * D_PROJ;
    const float* bcB   = projB + 2 * D_INNER + n * (2 * D_STATE + 1);
    const float* xB    = xconv + (size_t)(b * SEQLEN + t0) * D_INNER + n * HEADDIM + d;
    float* decB  = decay + ((size_t)bh * SEQLEN + t0) * D_STATE;
    float* ypB   = ypart + ((size_t)bh * SEQLEN + t0) * HEADDIM + d;

    float pB[4], pC[4], pDt[4], pX[4];
    float r = 1.f;                         // running decay cumprod (tid<64)

    {   // prologue: load steps 0..3; coefficients for step 0
        #pragma unroll
        for (int s = 0; s < 4; s++) {
            if (tid < D_STATE) {
                const float* bc = bcB + (size_t)s * D_PROJ;
                pB[s]  = bc[tid];
                pC[s]  = bc[D_STATE + tid];
                pDt[s] = bc[2 * D_STATE];
            }
            pX[s] = xB[(size_t)s * D_INNER];
        }
        if (tid < D_STATE) {
            float dtr = pDt[0] + dtb;
            float dt  = fmaxf(dtr, 0.f) + log1pf(expf(-fabsf(dtr)));
            float a   = expf(negA * dt);
            sA[0][tid] = a;
            sB[0][tid] = pB[0] * dt;
            sC[0][tid] = pC[0];
            r = a;
            if (dg == 0) decB[tid] = r;
        }
    }
    __syncthreads();

    float h[16];
    #pragma unroll
    for (int i = 0; i < 16; i++) h[i] = 0.f;

    const int s0 = q * 16;
    int buf = 0;

    #pragma unroll 4
    for (int t = 0; t < LSEG; t++) {
        const int slot  = t & 3;
        const int nslot = (t + 1) & 3;
        const float xv = pX[slot];

        if (t + 1 < LSEG && tid < D_STATE) {
            float dtr = pDt[nslot] + dtb;
            float dt  = fmaxf(dtr, 0.f) + log1pf(expf(-fabsf(dtr)));
            float a   = expf(negA * dt);
            sA[buf ^ 1][tid] = a;
            sB[buf ^ 1][tid] = pB[nslot] * dt;
            sC[buf ^ 1][tid] = pC[nslot];
            r *= a;
            if (dg == 0) decB[(size_t)(t + 1) * D_STATE + tid] = r;
        }

        if (t + 4 < LSEG) {
            const int tp = t + 4;
            if (tid < D_STATE) {
                const float* bc = bcB + (size_t)tp * D_PROJ;
                pB[slot]  = bc[tid];
                pC[slot]  = bc[D_STATE + tid];
                pDt[slot] = bc[2 * D_STATE];
            }
            pX[slot] = xB[(size_t)tp * D_INNER];
        }

        float a0 = 0.f, a1 = 0.f, a2 = 0.f, a3 = 0.f;
        #pragma unroll
        for (int j4 = 0; j4 < 4; j4++) {
            float4 a4 = *reinterpret_cast<const float4*>(&sA[buf][s0 + j4 * 4]);
            float4 b4 = *reinterpret_cast<const float4*>(&sB[buf][s0 + j4 * 4]);
            float4 c4 = *reinterpret_cast<const float4*>(&sC[buf][s0 + j4 * 4]);
            h[j4*4+0] = fmaf(a4.x, h[j4*4+0], b4.x * xv);
            h[j4*4+1] = fmaf(a4.y, h[j4*4+1], b4.y * xv);
            h[j4*4+2] = fmaf(a4.z, h[j4*4+2], b4.z * xv);
            h[j4*4+3] = fmaf(a4.w, h[j4*4+3], b4.w * xv);
            a0 = fmaf(c4.x, h[j4*4+0], a0);
            a1 = fmaf(c4.y, h[j4*4+1], a1);
            a2 = fmaf(c4.z, h[j4*4+2], a2);
            a3 = fmaf(c4.w, h[j4*4+3], a3);
        }
        float accv = (a0 + a1) + (a2 + a3);
        accv += __shfl_xor_sync(0xFFFFFFFFu, accv, 1);
        accv += __shfl_xor_sync(0xFFFFFFFFu, accv, 2);

        if (q == 0) ypB[(size_t)t * HEADDIM] = accv;
        __syncthreads();
        buf ^= 1;
    }

    // final zero-init state of this segment
    float* hs = hseg + (((size_t)bh * NSEG + seg) * D_STATE) * HEADDIM;
    #pragma unroll
    for (int j = 0; j < 16; j++)
        hs[(size_t)(s0 + j) * HEADDIM + d] = h[j];

    if (dg == 0 && tid < D_STATE)
        aprod[((size_t)bh * NSEG + seg) * D_STATE + tid] = r;
}

// ---------------- K2: combine segment states ---------------------------------
// grid NBH blocks, 256 threads. Each thread: one d, 16 s values.
__global__ __launch_bounds__(256)
void combine_kernel(const float* __restrict__ hseg,
                    const float* __restrict__ aprod,
                    float* __restrict__ hstart)
{
    const int bh  = blockIdx.x;
    const int tid = threadIdx.x;
    const int d   = tid & 63;
    const int sb  = (tid >> 6) * 16;      // states sb..sb+15

    float hs[16];
    #pragma unroll
    for (int j = 0; j < 16; j++) hs[j] = 0.f;

    // segment 0 starts from zero
    {
        float* dst = hstart + (((size_t)bh * NSEG) * D_STATE) * HEADDIM;
        #pragma unroll
        for (int j = 0; j < 16; j++)
            dst[(size_t)(sb + j) * HEADDIM + d] = 0.f;
    }
    for (int seg = 1; seg < NSEG; seg++) {
        const size_t prev = (size_t)bh * NSEG + seg - 1;
        const float* hp = hseg + prev * D_STATE * HEADDIM;
        const float* ap = aprod + prev * D_STATE;
        float* dst = hstart + (((size_t)bh * NSEG + seg) * D_STATE) * HEADDIM;
        #pragma unroll
        for (int j = 0; j < 16; j++) {
            hs[j] = fmaf(ap[sb + j], hs[j], hp[(size_t)(sb + j) * HEADDIM + d]);
            dst[(size_t)(sb + j) * HEADDIM + d] = hs[j];
        }
    }
}

// ---------------- K3: fixup + skip + gate + bf16 split -----------------------
// grid 1024 = (bh, seg), 128 threads = 2 token slots x 64 d.
__global__ __launch_bounds__(128)
void fixup_kernel(const float* __restrict__ proj,
                  const float* __restrict__ xconv,
                  const float* __restrict__ ypart,
                  const float* __restrict__ decay,
                  const float* __restrict__ hstart,
                  const float* __restrict__ Dp,
                  __nv_bfloat16* __restrict__ y_hi,
                  __nv_bfloat16* __restrict__ y_lo)
{
    const int blk = blockIdx.x;
    const int bh  = blk >> 4;
    const int seg = blk & 15;
    const int b   = bh / NHEADS;
    const int n   = bh % NHEADS;
    const int t0  = seg * LSEG;
    const int tid = threadIdx.x;
    const int tt  = tid >> 6;            // token slot 0/1
    const int d   = tid & 63;
    const float Dn = Dp[n];

    __shared__ float h0[D_STATE * HEADDIM];   // [s][d]
    __shared__ float w[2][D_STATE];

    {
        const float* src = hstart + (((size_t)bh * NSEG + seg) * D_STATE) * HEADDIM;
        for (int i = tid; i < D_STATE * HEADDIM; i += 128)
            h0[i] = src[i];
    }
    __syncthreads();

    for (int ti = 0; ti < LSEG; ti += 2) {
        // compute weights w[slot][s] = C_t[s] * decay[t][s]
        {
            const int tw = t0 + ti + tt;
            const int s  = d;
            const float* bc = proj + (size_t)(b * SEQLEN + tw) * D_PROJ
                              + 2 * D_INNER + n * (2 * D_STATE + 1);
            float Cs  = bc[D_STATE + s];
            float dec = decay[((size_t)bh * SEQLEN + tw) * D_STATE + s];
            w[tt][s] = Cs * dec;
        }
        __syncthreads();

        const int t = t0 + ti + tt;
        float yfix = 0.f;
        #pragma unroll
        for (int s = 0; s < D_STATE; s += 4) {
            yfix = fmaf(w[tt][s + 0], h0[(s + 0) * HEADDIM + d], yfix);
            yfix = fmaf(w[tt][s + 1], h0[(s + 1) * HEADDIM + d], yfix);
            yfix = fmaf(w[tt][s + 2], h0[(s + 2) * HEADDIM + d], yfix);
            yfix = fmaf(w[tt][s + 3], h0[(s + 3) * HEADDIM + d], yfix);
        }

        float yp = ypart[((size_t)bh * SEQLEN + t) * HEADDIM + d];
        float xv = xconv[(size_t)(b * SEQLEN + t) * D_INNER + n * HEADDIM + d];
        float zv = proj[(size_t)(b * SEQLEN + t) * D_PROJ + D_INNER + n * HEADDIM + d];
        float yv = yp + yfix + Dn * xv;
        float o  = yv * (zv / (1.f + expf(-zv)));
        __nv_bfloat16 oh = __float2bfloat16(o);
        size_t oi = (size_t)(b * SEQLEN + t) * D_INNER + n * HEADDIM + d;
        y_hi[oi] = oh;
        y_lo[oi] = __float2bfloat16(o - __bfloat162float(oh));
        __syncthreads();
    }
}

// ---------------- launcher ---------------------------------------------------
extern "C" void kernel_launch(void* const* d_in, const int* in_sizes, int n_in,
                              void* d_out, int out_size)
{
    const float* x       = (const float*)d_in[0];
    const float* W_in    = (const float*)d_in[1];
    const float* conv_w  = (const float*)d_in[2];
    const float* conv_b  = (const float*)d_in[3];
    const float* A_log   = (const float*)d_in[4];
    const float* Dp      = (const float*)d_in[5];
    const float* dt_bias = (const float*)d_in[6];
    const float* W_out   = (const float*)d_in[7];
    float* out = (float*)d_out;

    float *proj, *xconv, *ypart, *decay, *hseg, *hstart, *aprod;
    __nv_bfloat16 *xh, *xl, *wih, *wil, *woh, *wol, *yh, *yl;
    cudaGetSymbolAddress((void**)&proj,   g_proj);
    cudaGetSymbolAddress((void**)&xconv,  g_xconv);
    cudaGetSymbolAddress((void**)&ypart,  g_ypart);
    cudaGetSymbolAddress((void**)&decay,  g_decay);
    cudaGetSymbolAddress((void**)&hseg,   g_hseg);
    cudaGetSymbolAddress((void**)&hstart, g_hstart);
    cudaGetSymbolAddress((void**)&aprod,  g_aprod);
    cudaGetSymbolAddress((void**)&xh,  g_x_hi);    cudaGetSymbolAddress((void**)&xl,  g_x_lo);
    cudaGetSymbolAddress((void**)&wih, g_Win_hi);  cudaGetSymbolAddress((void**)&wil, g_Win_lo);
    cudaGetSymbolAddress((void**)&woh, g_Wout_hi); cudaGetSymbolAddress((void**)&wol, g_Wout_lo);
    cudaGetSymbolAddress((void**)&yh,  g_y_hi);    cudaGetSymbolAddress((void**)&yl,  g_y_lo);

    cudaFuncSetAttribute(gemm_mma, cudaFuncAttributeMaxDynamicSharedMemorySize, GEMM_SMEM);

    // 0) fp32 -> bf16 hi/lo splits (W_in zero-padded to 8320 rows)
    {
        int nx = NTOK * D_MODEL;
        split_bf16<<<(nx + 255) / 256, 256>>>(x, xh, xl, nx, nx);
        int nwi = D_PROJ * D_MODEL, nwp = NPROJ_PAD * D_MODEL;
        split_bf16<<<(nwp + 255) / 256, 256>>>(W_in, wih, wil, nwi, nwp);
        int nwo = D_MODEL * D_INNER;
        split_bf16<<<(nwo + 255) / 256, 256>>>(W_out, woh, wol, nwo, nwo);
    }
    // 1) proj = x @ W_in^T
    {
        dim3 grid(NPROJ_PAD / 128, NTOK / 128);
        gemm_mma<<<grid, 256, GEMM_SMEM>>>(xh, xl, wih, wil, proj, NTOK, D_PROJ, D_MODEL);
    }
    // 2) conv + silu
    {
        int total = NTOK * D_INNER;
        conv_silu_kernel<<<(total + 255) / 256, 256>>>(proj, conv_w, conv_b, xconv);
    }
    // 3) segmented scan: K1 (parallel zero-init scans) -> K2 (state combine)
    //    -> K3 (fixup + skip + gate, emits y bf16 hi/lo)
    {
        seg_scan_kernel<<<NBH * NSEG * 2, 128>>>(proj, xconv, A_log, dt_bias,
                                                 ypart, decay, hseg, aprod);
        combine_kernel<<<NBH, 256>>>(hseg, aprod, hstart);
        fixup_kernel<<<NBH * NSEG, 128>>>(proj, xconv, ypart, decay, hstart, Dp, yh, yl);
    }
    // 4) out = y @ W_out^T
    {
        dim3 grid(D_MODEL / 128, NTOK / 128);
        gemm_mma<<<grid, 256, GEMM_SMEM>>>(yh, yl, woh, wol, out, NTOK, D_MODEL, D_INNER);
    }
}

// round 15
// speedup vs baseline: 3.2149x; 1.0991x over previous
#include <cuda_runtime.h>
#include <cuda_bf16.h>
#include <math.h>
#include <stdint.h>

#define D_MODEL   1024
#define D_STATE   64
#define D_CONV    4
#define D_INNER   2048
#define NHEADS    32
#define HEADDIM   64
#define D_PROJ    8224
#define BATCH     2
#define SEQLEN    1024
#define NTOK      (BATCH*SEQLEN)     // 2048
#define NPROJ_PAD 8320               // D_PROJ padded to 65*128
#define NBH       (BATCH*NHEADS)     // 64
#define NSEG      16
#define LSEG      64                 // SEQLEN / NSEG

// ---------------- scratch (static device allocations) ----------------------
__device__ float g_proj [(size_t)NTOK * D_PROJ];
__device__ float g_xconv[(size_t)NTOK * D_INNER];
__device__ __nv_bfloat16 g_x_hi  [(size_t)NTOK * D_MODEL];
__device__ __nv_bfloat16 g_x_lo  [(size_t)NTOK * D_MODEL];
__device__ __nv_bfloat16 g_Win_hi[(size_t)NPROJ_PAD * D_MODEL];
__device__ __nv_bfloat16 g_Win_lo[(size_t)NPROJ_PAD * D_MODEL];
__device__ __nv_bfloat16 g_Wout_hi[(size_t)D_MODEL * D_INNER];
__device__ __nv_bfloat16 g_Wout_lo[(size_t)D_MODEL * D_INNER];
__device__ __nv_bfloat16 g_y_hi  [(size_t)NTOK * D_INNER];
__device__ __nv_bfloat16 g_y_lo  [(size_t)NTOK * D_INNER];
// segmented-scan scratch
__device__ float g_ypart [(size_t)NBH * SEQLEN * HEADDIM];
__device__ float g_decay [(size_t)NBH * SEQLEN * D_STATE];
__device__ float g_hseg  [(size_t)NBH * NSEG * D_STATE * HEADDIM];
__device__ float g_hstart[(size_t)NBH * NSEG * D_STATE * HEADDIM];
__device__ float g_aprod [(size_t)NBH * NSEG * D_STATE];

// ---------------- helpers ---------------------------------------------------
__device__ __forceinline__ uint32_t smem_u32(const void* p) {
    uint32_t a;
    asm("{ .reg .u64 t; cvta.to.shared.u64 t, %1; cvt.u32.u64 %0, t; }" : "=r"(a) : "l"(p));
    return a;
}
#define CP_ASYNC16(dst, src) \
    asm volatile("cp.async.cg.shared.global [%0], [%1], 16;" :: "r"(dst), "l"(src) : "memory")
#define CP_COMMIT() asm volatile("cp.async.commit_group;" ::: "memory")

__device__ __forceinline__ void ldmatrix_x4(uint32_t* r, uint32_t addr) {
    asm volatile("ldmatrix.sync.aligned.m8n8.x4.shared.b16 {%0,%1,%2,%3}, [%4];"
        : "=r"(r[0]), "=r"(r[1]), "=r"(r[2]), "=r"(r[3]) : "r"(addr));
}
__device__ __forceinline__ void mma16816(float* c, const uint32_t* a, const uint32_t* b) {
    asm volatile("mma.sync.aligned.m16n8k16.row.col.f32.bf16.bf16.f32 "
        "{%0,%1,%2,%3}, {%4,%5,%6,%7}, {%8,%9}, {%0,%1,%2,%3};"
        : "+f"(c[0]), "+f"(c[1]), "+f"(c[2]), "+f"(c[3])
        : "r"(a[0]), "r"(a[1]), "r"(a[2]), "r"(a[3]), "r"(b[0]), "r"(b[1]));
}

// XOR-swizzled smem offset for 64B rows: 4 chunks of 16B, chunk' = chunk ^ ((row>>1)&3)
__device__ __forceinline__ uint32_t sw_off(int row, int chunk) {
    return (uint32_t)(row * 64 + ((chunk ^ ((row >> 1) & 3)) << 4));
}

// ---------------- fused fp32 -> bf16 hi/lo splits (x, W_in pad, W_out) -------
#define NX_ELEM  (NTOK * D_MODEL)
#define NWI_ELEM (D_PROJ * D_MODEL)
#define NWP_ELEM (NPROJ_PAD * D_MODEL)
#define NWO_ELEM (D_MODEL * D_INNER)
__global__ void split_all(const float* __restrict__ x, const float* __restrict__ Wi,
                          const float* __restrict__ Wo,
                          __nv_bfloat16* __restrict__ xh, __nv_bfloat16* __restrict__ xl,
                          __nv_bfloat16* __restrict__ wih, __nv_bfloat16* __restrict__ wil,
                          __nv_bfloat16* __restrict__ woh, __nv_bfloat16* __restrict__ wol)
{
    int i = blockIdx.x * blockDim.x + threadIdx.x;
    __nv_bfloat16 *dh, *dl; int idx; float v;
    if (i < NX_ELEM) {
        idx = i; dh = xh; dl = xl; v = x[idx];
    } else if (i < NX_ELEM + NWP_ELEM) {
        idx = i - NX_ELEM; dh = wih; dl = wil;
        v = (idx < NWI_ELEM) ? Wi[idx] : 0.f;
    } else if (i < NX_ELEM + NWP_ELEM + NWO_ELEM) {
        idx = i - NX_ELEM - NWP_ELEM; dh = woh; dl = wol; v = Wo[idx];
    } else return;
    __nv_bfloat16 h = __float2bfloat16(v);
    dh[idx] = h;
    dl[idx] = __float2bfloat16(v - __bfloat162float(h));
}

// ---------------- split-bf16 tensor-core GEMM (NT) via mma.sync --------------
// 3-stage cp.async ring, ONE __syncthreads per K-iteration, XOR-swizzled smem
// (64B rows, no padding -> 16B-aligned addresses, conflict-free ldmatrix).
#define TILE_B  (128 * 64)             // 8192
#define STAGE_B (4 * TILE_B)           // 32768 (Ah, Al, Bh, Bl)
#define NSTAGE  3
#define GEMM_SMEM (NSTAGE * STAGE_B)   // 98304; x2 CTAs = 192KB <= 228KB

__global__ __launch_bounds__(256, 2)
void gemm_mma(const __nv_bfloat16* __restrict__ Ah, const __nv_bfloat16* __restrict__ Al,
              const __nv_bfloat16* __restrict__ Bh, const __nv_bfloat16* __restrict__ Bl,
              float* __restrict__ C, int M, int N, int K)
{
    extern __shared__ char smem[];
    const uint32_t sb = smem_u32(smem);
    const int tid  = threadIdx.x;
    const int lane = tid & 31;
    const int wid  = tid >> 5;
    const int wm   = wid & 3;
    const int wn   = wid >> 2;

    const int m0 = blockIdx.y * 128;
    const int n0 = blockIdx.x * 128;
    const int T  = K / 32;

    const __nv_bfloat16* gsrc[4] = {Ah, Al, Bh, Bl};
    const int grow[4] = {m0, m0, n0, n0};

    const int lr = tid >> 2;          // 0..63
    const int lc = tid & 3;           // chunk 0..3
    // swizzle invariant under row+64 ((r+64)>>1 changes by 32, mod 4 = 0)
    const uint32_t soff = sw_off(lr, lc);
    auto load_stage = [&](int stg, int k0) {
        uint32_t base = sb + stg * STAGE_B;
        #pragma unroll
        for (int ts = 0; ts < 4; ts++) {
            const __nv_bfloat16* g = gsrc[ts] + (size_t)(grow[ts] + lr) * K + k0 + lc * 8;
            uint32_t dst = base + ts * TILE_B + soff;
            CP_ASYNC16(dst, g);
            CP_ASYNC16(dst + 64 * 64, g + (size_t)64 * K);
        }
    };

    // prologue: stages 0,1 in flight
    load_stage(0, 0);  CP_COMMIT();
    if (T > 1) { load_stage(1, 32); CP_COMMIT(); }

    float acc[2][8][4];
    #pragma unroll
    for (int i = 0; i < 2; i++)
        #pragma unroll
        for (int j = 0; j < 8; j++)
            #pragma unroll
            for (int k = 0; k < 4; k++) acc[i][j][k] = 0.f;

    const int a_row = wm * 32 + (lane & 15);
    const int a_k   = (lane >> 4) << 3;                 // 0 / 8 (bf16 elems)
    const int b_row = wn * 64 + (lane & 7) + ((lane & 16) >> 1);
    const int b_k   = lane & 8;

    int stage = 0;
    for (int t = 0; t < T; t++) {
        if (t + 1 < T) asm volatile("cp.async.wait_group 1;" ::: "memory");
        else           asm volatile("cp.async.wait_group 0;" ::: "memory");
        __syncthreads();   // publish stage t; all warps done reading stage (t-1)%3

        if (t + 2 < T) {
            int ns = stage + 2; if (ns >= NSTAGE) ns -= NSTAGE;
            load_stage(ns, (t + 2) * 32);
            CP_COMMIT();
        }

        const uint32_t st = sb + stage * STAGE_B;
        #pragma unroll
        for (int kk = 0; kk < 32; kk += 16) {
            #pragma unroll
            for (int sp = 0; sp < 3; sp++) {
                const uint32_t Ab = st + ((sp == 2) ? TILE_B : 0);
                const uint32_t Bb = st + 2 * TILE_B + ((sp == 1) ? TILE_B : 0);
                const int ac = (kk + a_k) >> 3;          // chunk 0..3
                const int bc = (kk + b_k) >> 3;
                uint32_t a[2][4];
                #pragma unroll
                for (int mf = 0; mf < 2; mf++)
                    ldmatrix_x4(a[mf], Ab + sw_off(a_row + mf * 16, ac));
                uint32_t b[8][2];
                #pragma unroll
                for (int nb = 0; nb < 4; nb++) {
                    uint32_t r[4];
                    ldmatrix_x4(r, Bb + sw_off(b_row + nb * 16, bc));
                    b[nb * 2][0] = r[0]; b[nb * 2][1] = r[1];
                    b[nb * 2 + 1][0] = r[2]; b[nb * 2 + 1][1] = r[3];
                }
                #pragma unroll
                for (int mf = 0; mf < 2; mf++)
                    #pragma unroll
                    for (int nf = 0; nf < 8; nf++)
                        mma16816(acc[mf][nf], a[mf], b[nf]);
            }
        }
        if (++stage >= NSTAGE) stage = 0;
    }

    #pragma unroll
    for (int mf = 0; mf < 2; mf++) {
        const int r0 = m0 + wm * 32 + mf * 16 + (lane >> 2);
        #pragma unroll
        for (int nf = 0; nf < 8; nf++) {
            const int col = n0 + wn * 64 + nf * 8 + (lane & 3) * 2;
            if (col < N) {
                float2 v0 = make_float2(acc[mf][nf][0], acc[mf][nf][1]);
                float2 v1 = make_float2(acc[mf][nf][2], acc[mf][nf][3]);
                *reinterpret_cast<float2*>(&C[(size_t)r0 * N + col]) = v0;
                *reinterpret_cast<float2*>(&C[(size_t)(r0 + 8) * N + col]) = v1;
            }
        }
    }
}

// ---------------- K1: segmented scan with fused conv+SiLU --------------------
__global__ __launch_bounds__(128)
void seg_scan_kernel(const float* __restrict__ proj,
                     const float* __restrict__ conv_w,
                     const float* __restrict__ conv_b,
                     const float* __restrict__ A_log,
                     const float* __restrict__ dt_bias,
                     float* __restrict__ xconv,
                     float* __restrict__ ypart,
                     float* __restrict__ decay,
                     float* __restrict__ hseg,
                     float* __restrict__ aprod)
{
    const int blk = blockIdx.x;
    const int bh  = blk >> 5;
    const int rem = blk & 31;
    const int seg = rem >> 1;
    const int dg  = rem & 1;
    const int b   = bh / NHEADS;
    const int n   = bh % NHEADS;
    const int tid = threadIdx.x;
    const int dl  = tid >> 2;
    const int q   = tid & 3;
    const int d   = dg * 32 + dl;
    const int c   = n * HEADDIM + d;
    const int t0  = seg * LSEG;

    __shared__ float sA[2][D_STATE];
    __shared__ float sB[2][D_STATE];
    __shared__ float sC[2][D_STATE];

    float negA = 0.f;
    if (tid < D_STATE) negA = -expf(A_log[n * D_STATE + tid]);
    const float dtb = dt_bias[n];

    const float cw0 = conv_w[c * D_CONV + 0];
    const float cw1 = conv_w[c * D_CONV + 1];
    const float cw2 = conv_w[c * D_CONV + 2];
    const float cw3 = conv_w[c * D_CONV + 3];
    const float cb  = conv_b[c];

    const float* projB = proj + (size_t)(b * SEQLEN + t0) * D_PROJ;
    const float* bcB   = projB + 2 * D_INNER + n * (2 * D_STATE + 1);
    const float* xiB   = projB + c;
    float* decB  = decay + ((size_t)bh * SEQLEN + t0) * D_STATE;
    float* ypB   = ypart + ((size_t)bh * SEQLEN + t0) * HEADDIM + d;
    float* xcB   = xconv + (size_t)(b * SEQLEN + t0) * D_INNER + c;

    float pB[4], pC[4], pDt[4], pXI[4];
    float xw0, xw1, xw2, xw3;
    float r = 1.f;

    {   // prologue
        #pragma unroll
        for (int s = 0; s < 4; s++) {
            if (tid < D_STATE) {
                const float* bc = bcB + (size_t)s * D_PROJ;
                pB[s]  = bc[tid];
                pC[s]  = bc[D_STATE + tid];
                pDt[s] = bc[2 * D_STATE];
            }
        }
        xw0 = (t0 >= 3) ? xiB[(size_t)(-3) * D_PROJ] : 0.f;
        xw1 = (t0 >= 2) ? xiB[(size_t)(-2) * D_PROJ] : 0.f;
        xw2 = (t0 >= 1) ? xiB[(size_t)(-1) * D_PROJ] : 0.f;
        xw3 = xiB[0];
        pXI[1] = xiB[(size_t)1 * D_PROJ];
        pXI[2] = xiB[(size_t)2 * D_PROJ];
        pXI[3] = xiB[(size_t)3 * D_PROJ];
        pXI[0] = 0.f;
        if (tid < D_STATE) {
            float dtr = pDt[0] + dtb;
            float dt  = fmaxf(dtr, 0.f) + log1pf(expf(-fabsf(dtr)));
            float a   = expf(negA * dt);
            sA[0][tid] = a;
            sB[0][tid] = pB[0] * dt;
            sC[0][tid] = pC[0];
            r = a;
            if (dg == 0) decB[tid] = r;
        }
    }
    __syncthreads();

    float h[16];
    #pragma unroll
    for (int i = 0; i < 16; i++) h[i] = 0.f;

    const int s0 = q * 16;
    int buf = 0;

    #pragma unroll 4
    for (int t = 0; t < LSEG; t++) {
        const int slot  = t & 3;
        const int nslot = (t + 1) & 3;

        float xc = cb;
        xc = fmaf(cw0, xw0, xc);
        xc = fmaf(cw1, xw1, xc);
        xc = fmaf(cw2, xw2, xc);
        xc = fmaf(cw3, xw3, xc);
        const float xv = xc / (1.f + expf(-xc));

        if (t + 1 < LSEG && tid < D_STATE) {
            float dtr = pDt[nslot] + dtb;
            float dt  = fmaxf(dtr, 0.f) + log1pf(expf(-fabsf(dtr)));
            float a   = expf(negA * dt);
            sA[buf ^ 1][tid] = a;
            sB[buf ^ 1][tid] = pB[nslot] * dt;
            sC[buf ^ 1][tid] = pC[nslot];
            r *= a;
            if (dg == 0) decB[(size_t)(t + 1) * D_STATE + tid] = r;
        }

        if (t + 4 < LSEG) {
            const int tp = t + 4;
            if (tid < D_STATE) {
                const float* bc = bcB + (size_t)tp * D_PROJ;
                pB[slot]  = bc[tid];
                pC[slot]  = bc[D_STATE + tid];
                pDt[slot] = bc[2 * D_STATE];
            }
            pXI[slot] = xiB[(size_t)tp * D_PROJ];
        }

        float a0 = 0.f, a1 = 0.f, a2 = 0.f, a3 = 0.f;
        #pragma unroll
        for (int j4 = 0; j4 < 4; j4++) {
            float4 a4 = *reinterpret_cast<const float4*>(&sA[buf][s0 + j4 * 4]);
            float4 b4 = *reinterpret_cast<const float4*>(&sB[buf][s0 + j4 * 4]);
            float4 c4 = *reinterpret_cast<const float4*>(&sC[buf][s0 + j4 * 4]);
            h[j4*4+0] = fmaf(a4.x, h[j4*4+0], b4.x * xv);
            h[j4*4+1] = fmaf(a4.y, h[j4*4+1], b4.y * xv);
            h[j4*4+2] = fmaf(a4.z, h[j4*4+2], b4.z * xv);
            h[j4*4+3] = fmaf(a4.w, h[j4*4+3], b4.w * xv);
            a0 = fmaf(c4.x, h[j4*4+0], a0);
            a1 = fmaf(c4.y, h[j4*4+1], a1);
            a2 = fmaf(c4.z, h[j4*4+2], a2);
            a3 = fmaf(c4.w, h[j4*4+3], a3);
        }
        float accv = (a0 + a1) + (a2 + a3);
        accv += __shfl_xor_sync(0xFFFFFFFFu, accv, 1);
        accv += __shfl_xor_sync(0xFFFFFFFFu, accv, 2);

        if (q == 0) {
            ypB[(size_t)t * HEADDIM] = accv;
            xcB[(size_t)t * D_INNER] = xv;
        }
        xw0 = xw1; xw1 = xw2; xw2 = xw3; xw3 = pXI[nslot];
        __syncthreads();
        buf ^= 1;
    }

    float* hs = hseg + (((size_t)bh * NSEG + seg) * D_STATE) * HEADDIM;
    #pragma unroll
    for (int j = 0; j < 16; j++)
        hs[(size_t)(s0 + j) * HEADDIM + d] = h[j];

    if (dg == 0 && tid < D_STATE)
        aprod[((size_t)bh * NSEG + seg) * D_STATE + tid] = r;
}

// ---------------- K2: combine segment states ---------------------------------
__global__ __launch_bounds__(256)
void combine_kernel(const float* __restrict__ hseg,
                    const float* __restrict__ aprod,
                    float* __restrict__ hstart)
{
    const int bh  = blockIdx.x;
    const int tid = threadIdx.x;
    const int d   = tid & 63;
    const int sb  = (tid >> 6) * 16;

    float hs[16];
    #pragma unroll
    for (int j = 0; j < 16; j++) hs[j] = 0.f;

    {
        float* dst = hstart + (((size_t)bh * NSEG) * D_STATE) * HEADDIM;
        #pragma unroll
        for (int j = 0; j < 16; j++)
            dst[(size_t)(sb + j) * HEADDIM + d] = 0.f;
    }
    for (int seg = 1; seg < NSEG; seg++) {
        const size_t prev = (size_t)bh * NSEG + seg - 1;
        const float* hp = hseg + prev * D_STATE * HEADDIM;
        const float* ap = aprod + prev * D_STATE;
        float* dst = hstart + (((size_t)bh * NSEG + seg) * D_STATE) * HEADDIM;
        #pragma unroll
        for (int j = 0; j < 16; j++) {
            hs[j] = fmaf(ap[sb + j], hs[j], hp[(size_t)(sb + j) * HEADDIM + d]);
            dst[(size_t)(sb + j) * HEADDIM + d] = hs[j];
        }
    }
}

// ---------------- K3: fixup + skip + gate + bf16 split -----------------------
__global__ __launch_bounds__(128)
void fixup_kernel(const float* __restrict__ proj,
                  const float* __restrict__ xconv,
                  const float* __restrict__ ypart,
                  const float* __restrict__ decay,
                  const float* __restrict__ hstart,
                  const float* __restrict__ Dp,
                  __nv_bfloat16* __restrict__ y_hi,
                  __nv_bfloat16* __restrict__ y_lo)
{
    const int blk = blockIdx.x;
    const int bh  = blk >> 4;
    const int seg = blk & 15;
    const int b   = bh / NHEADS;
    const int n   = bh % NHEADS;
    const int t0  = seg * LSEG;
    const int tid = threadIdx.x;
    const int tt  = tid >> 6;
    const int d   = tid & 63;
    const float Dn = Dp[n];

    __shared__ float h0[D_STATE * HEADDIM];
    __shared__ float w[2][D_STATE];

    {
        const float* src = hstart + (((size_t)bh * NSEG + seg) * D_STATE) * HEADDIM;
        for (int i = tid; i < D_STATE * HEADDIM; i += 128)
            h0[i] = src[i];
    }
    __syncthreads();

    for (int ti = 0; ti < LSEG; ti += 2) {
        {
            const int tw = t0 + ti + tt;
            const int s  = d;
            const float* bc = proj + (size_t)(b * SEQLEN + tw) * D_PROJ
                              + 2 * D_INNER + n * (2 * D_STATE + 1);
            float Cs  = bc[D_STATE + s];
            float dec = decay[((size_t)bh * SEQLEN + tw) * D_STATE + s];
            w[tt][s] = Cs * dec;
        }
        __syncthreads();

        const int t = t0 + ti + tt;
        float yfix = 0.f;
        #pragma unroll
        for (int s = 0; s < D_STATE; s += 4) {
            yfix = fmaf(w[tt][s + 0], h0[(s + 0) * HEADDIM + d], yfix);
            yfix = fmaf(w[tt][s + 1], h0[(s + 1) * HEADDIM + d], yfix);
            yfix = fmaf(w[tt][s + 2], h0[(s + 2) * HEADDIM + d], yfix);
            yfix = fmaf(w[tt][s + 3], h0[(s + 3) * HEADDIM + d], yfix);
        }

        float yp = ypart[((size_t)bh * SEQLEN + t) * HEADDIM + d];
        float xv = xconv[(size_t)(b * SEQLEN + t) * D_INNER + n * HEADDIM + d];
        float zv = proj[(size_t)(b * SEQLEN + t) * D_PROJ + D_INNER + n * HEADDIM + d];
        float yv = yp + yfix + Dn * xv;
        float o  = yv * (zv / (1.f + expf(-zv)));
        __nv_bfloat16 oh = __float2bfloat16(o);
        size_t oi = (size_t)(b * SEQLEN + t) * D_INNER + n * HEADDIM + d;
        y_hi[oi] = oh;
        y_lo[oi] = __float2bfloat16(o - __bfloat162float(oh));
        __syncthreads();
    }
}

// ---------------- launcher ---------------------------------------------------
extern "C" void kernel_launch(void* const* d_in, const int* in_sizes, int n_in,
                              void* d_out, int out_size)
{
    const float* x       = (const float*)d_in[0];
    const float* W_in    = (const float*)d_in[1];
    const float* conv_w  = (const float*)d_in[2];
    const float* conv_b  = (const float*)d_in[3];
    const float* A_log   = (const float*)d_in[4];
    const float* Dp      = (const float*)d_in[5];
    const float* dt_bias = (const float*)d_in[6];
    const float* W_out   = (const float*)d_in[7];
    float* out = (float*)d_out;

    float *proj, *xconv, *ypart, *decay, *hseg, *hstart, *aprod;
    __nv_bfloat16 *xh, *xl, *wih, *wil, *woh, *wol, *yh, *yl;
    cudaGetSymbolAddress((void**)&proj,   g_proj);
    cudaGetSymbolAddress((void**)&xconv,  g_xconv);
    cudaGetSymbolAddress((void**)&ypart,  g_ypart);
    cudaGetSymbolAddress((void**)&decay,  g_decay);
    cudaGetSymbolAddress((void**)&hseg,   g_hseg);
    cudaGetSymbolAddress((void**)&hstart, g_hstart);
    cudaGetSymbolAddress((void**)&aprod,  g_aprod);
    cudaGetSymbolAddress((void**)&xh,  g_x_hi);    cudaGetSymbolAddress((void**)&xl,  g_x_lo);
    cudaGetSymbolAddress((void**)&wih, g_Win_hi);  cudaGetSymbolAddress((void**)&wil, g_Win_lo);
    cudaGetSymbolAddress((void**)&woh, g_Wout_hi); cudaGetSymbolAddress((void**)&wol, g_Wout_lo);
    cudaGetSymbolAddress((void**)&yh,  g_y_hi);    cudaGetSymbolAddress((void**)&yl,  g_y_lo);

    cudaFuncSetAttribute(gemm_mma, cudaFuncAttributeMaxDynamicSharedMemorySize, GEMM_SMEM);

    // 0) fused fp32 -> bf16 hi/lo splits
    {
        long total = (long)NX_ELEM + NWP_ELEM + NWO_ELEM;
        split_all<<<(int)((total + 255) / 256), 256>>>(x, W_in, W_out,
                                                       xh, xl, wih, wil, woh, wol);
    }
    // 1) proj = x @ W_in^T
    {
        dim3 grid(NPROJ_PAD / 128, NTOK / 128);
        gemm_mma<<<grid, 256, GEMM_SMEM>>>(xh, xl, wih, wil, proj, NTOK, D_PROJ, D_MODEL);
    }
    // 2) segmented scan (conv fused): K1 -> K2 -> K3
    {
        seg_scan_kernel<<<NBH * NSEG * 2, 128>>>(proj, conv_w, conv_b, A_log, dt_bias,
                                                 xconv, ypart, decay, hseg, aprod);
        combine_kernel<<<NBH, 256>>>(hseg, aprod, hstart);
        fixup_kernel<<<NBH * NSEG, 128>>>(proj, xconv, ypart, decay, hstart, Dp, yh, yl);
    }
    // 3) out = y @ W_out^T
    {
        dim3 grid(D_MODEL / 128, NTOK / 128);
        gemm_mma<<<grid, 256, GEMM_SMEM>>>(yh, yl, woh, wol, out, NTOK, D_MODEL, D_INNER);
    }
}

// round 16
// speedup vs baseline: 3.3834x; 1.0524x over previous
#include <cuda_runtime.h>
#include <cuda_bf16.h>
#include <math.h>
#include <stdint.h>

#define D_MODEL   1024
#define D_STATE   64
#define D_CONV    4
#define D_INNER   2048
#define NHEADS    32
#define HEADDIM   64
#define D_PROJ    8224
#define BATCH     2
#define SEQLEN    1024
#define NTOK      (BATCH*SEQLEN)     // 2048
#define NPROJ_PAD 8320               // D_PROJ padded to 65*128
#define NBH       (BATCH*NHEADS)     // 64
#define NSEG      16
#define LSEG      64                 // SEQLEN / NSEG

// ---------------- scratch (static device allocations) ----------------------
__device__ float g_proj [(size_t)NTOK * D_PROJ];
__device__ float g_xconv[(size_t)NTOK * D_INNER];
__device__ __nv_bfloat16 g_x_hi  [(size_t)NTOK * D_MODEL];
__device__ __nv_bfloat16 g_x_lo  [(size_t)NTOK * D_MODEL];
__device__ __nv_bfloat16 g_Win_hi[(size_t)NPROJ_PAD * D_MODEL];
__device__ __nv_bfloat16 g_Win_lo[(size_t)NPROJ_PAD * D_MODEL];
__device__ __nv_bfloat16 g_Wout_hi[(size_t)D_MODEL * D_INNER];
__device__ __nv_bfloat16 g_Wout_lo[(size_t)D_MODEL * D_INNER];
__device__ __nv_bfloat16 g_y_hi  [(size_t)NTOK * D_INNER];
__device__ __nv_bfloat16 g_y_lo  [(size_t)NTOK * D_INNER];
// segmented-scan scratch
__device__ float g_ypart [(size_t)NBH * SEQLEN * HEADDIM];
__device__ float g_decay [(size_t)NBH * SEQLEN * D_STATE];
__device__ float g_hseg  [(size_t)NBH * NSEG * D_STATE * HEADDIM];
__device__ float g_hstart[(size_t)NBH * NSEG * D_STATE * HEADDIM];
__device__ float g_aprod [(size_t)NBH * NSEG * D_STATE];

// ---------------- helpers ---------------------------------------------------
__device__ __forceinline__ uint32_t smem_u32(const void* p) {
    uint32_t a;
    asm("{ .reg .u64 t; cvta.to.shared.u64 t, %1; cvt.u32.u64 %0, t; }" : "=r"(a) : "l"(p));
    return a;
}
#define CP_ASYNC16(dst, src) \
    asm volatile("cp.async.cg.shared.global [%0], [%1], 16;" :: "r"(dst), "l"(src) : "memory")
#define CP_COMMIT() asm volatile("cp.async.commit_group;" ::: "memory")

__device__ __forceinline__ void ldmatrix_x4(uint32_t* r, uint32_t addr) {
    asm volatile("ldmatrix.sync.aligned.m8n8.x4.shared.b16 {%0,%1,%2,%3}, [%4];"
        : "=r"(r[0]), "=r"(r[1]), "=r"(r[2]), "=r"(r[3]) : "r"(addr));
}
__device__ __forceinline__ void mma16816(float* c, const uint32_t* a, const uint32_t* b) {
    asm volatile("mma.sync.aligned.m16n8k16.row.col.f32.bf16.bf16.f32 "
        "{%0,%1,%2,%3}, {%4,%5,%6,%7}, {%8,%9}, {%0,%1,%2,%3};"
        : "+f"(c[0]), "+f"(c[1]), "+f"(c[2]), "+f"(c[3])
        : "r"(a[0]), "r"(a[1]), "r"(a[2]), "r"(a[3]), "r"(b[0]), "r"(b[1]));
}

// XOR-swizzled smem offset for 64B rows: 4 chunks of 16B, chunk' = chunk ^ ((row>>1)&3)
__device__ __forceinline__ uint32_t sw_off(int row, int chunk) {
    return (uint32_t)(row * 64 + ((chunk ^ ((row >> 1) & 3)) << 4));
}

// ---------------- fused fp32 -> bf16 hi/lo splits (x, W_in pad, W_out) -------
#define NX_ELEM  (NTOK * D_MODEL)
#define NWI_ELEM (D_PROJ * D_MODEL)
#define NWP_ELEM (NPROJ_PAD * D_MODEL)
#define NWO_ELEM (D_MODEL * D_INNER)
__global__ void split_all(const float* __restrict__ x, const float* __restrict__ Wi,
                          const float* __restrict__ Wo,
                          __nv_bfloat16* __restrict__ xh, __nv_bfloat16* __restrict__ xl,
                          __nv_bfloat16* __restrict__ wih, __nv_bfloat16* __restrict__ wil,
                          __nv_bfloat16* __restrict__ woh, __nv_bfloat16* __restrict__ wol)
{
    int i = blockIdx.x * blockDim.x + threadIdx.x;
    __nv_bfloat16 *dh, *dl; int idx; float v;
    if (i < NX_ELEM) {
        idx = i; dh = xh; dl = xl; v = x[idx];
    } else if (i < NX_ELEM + NWP_ELEM) {
        idx = i - NX_ELEM; dh = wih; dl = wil;
        v = (idx < NWI_ELEM) ? Wi[idx] : 0.f;
    } else if (i < NX_ELEM + NWP_ELEM + NWO_ELEM) {
        idx = i - NX_ELEM - NWP_ELEM; dh = woh; dl = wol; v = Wo[idx];
    } else return;
    __nv_bfloat16 h = __float2bfloat16(v);
    dh[idx] = h;
    dl[idx] = __float2bfloat16(v - __bfloat162float(h));
}

// ---------------- split-bf16 tensor-core GEMM (NT) via mma.sync --------------
// 3-stage cp.async ring, ONE __syncthreads per K-iteration, XOR-swizzled smem.
#define TILE_B  (128 * 64)             // 8192
#define STAGE_B (4 * TILE_B)           // 32768 (Ah, Al, Bh, Bl)
#define NSTAGE  3
#define GEMM_SMEM (NSTAGE * STAGE_B)   // 98304; x2 CTAs = 192KB <= 228KB

__global__ __launch_bounds__(256, 2)
void gemm_mma(const __nv_bfloat16* __restrict__ Ah, const __nv_bfloat16* __restrict__ Al,
              const __nv_bfloat16* __restrict__ Bh, const __nv_bfloat16* __restrict__ Bl,
              float* __restrict__ C, int M, int N, int K)
{
    extern __shared__ char smem[];
    const uint32_t sb = smem_u32(smem);
    const int tid  = threadIdx.x;
    const int lane = tid & 31;
    const int wid  = tid >> 5;
    const int wm   = wid & 3;
    const int wn   = wid >> 2;

    const int m0 = blockIdx.y * 128;
    const int n0 = blockIdx.x * 128;
    const int T  = K / 32;

    const __nv_bfloat16* gsrc[4] = {Ah, Al, Bh, Bl};
    const int grow[4] = {m0, m0, n0, n0};

    const int lr = tid >> 2;
    const int lc = tid & 3;
    const uint32_t soff = sw_off(lr, lc);
    auto load_stage = [&](int stg, int k0) {
        uint32_t base = sb + stg * STAGE_B;
        #pragma unroll
        for (int ts = 0; ts < 4; ts++) {
            const __nv_bfloat16* g = gsrc[ts] + (size_t)(grow[ts] + lr) * K + k0 + lc * 8;
            uint32_t dst = base + ts * TILE_B + soff;
            CP_ASYNC16(dst, g);
            CP_ASYNC16(dst + 64 * 64, g + (size_t)64 * K);
        }
    };

    load_stage(0, 0);  CP_COMMIT();
    if (T > 1) { load_stage(1, 32); CP_COMMIT(); }

    float acc[2][8][4];
    #pragma unroll
    for (int i = 0; i < 2; i++)
        #pragma unroll
        for (int j = 0; j < 8; j++)
            #pragma unroll
            for (int k = 0; k < 4; k++) acc[i][j][k] = 0.f;

    const int a_row = wm * 32 + (lane & 15);
    const int a_k   = (lane >> 4) << 3;
    const int b_row = wn * 64 + (lane & 7) + ((lane & 16) >> 1);
    const int b_k   = lane & 8;

    int stage = 0;
    for (int t = 0; t < T; t++) {
        if (t + 1 < T) asm volatile("cp.async.wait_group 1;" ::: "memory");
        else           asm volatile("cp.async.wait_group 0;" ::: "memory");
        __syncthreads();

        if (t + 2 < T) {
            int ns = stage + 2; if (ns >= NSTAGE) ns -= NSTAGE;
            load_stage(ns, (t + 2) * 32);
            CP_COMMIT();
        }

        const uint32_t st = sb + stage * STAGE_B;
        #pragma unroll
        for (int kk = 0; kk < 32; kk += 16) {
            #pragma unroll
            for (int sp = 0; sp < 3; sp++) {
                const uint32_t Ab = st + ((sp == 2) ? TILE_B : 0);
                const uint32_t Bb = st + 2 * TILE_B + ((sp == 1) ? TILE_B : 0);
                const int ac = (kk + a_k) >> 3;
                const int bc = (kk + b_k) >> 3;
                uint32_t a[2][4];
                #pragma unroll
                for (int mf = 0; mf < 2; mf++)
                    ldmatrix_x4(a[mf], Ab + sw_off(a_row + mf * 16, ac));
                uint32_t b[8][2];
                #pragma unroll
                for (int nb = 0; nb < 4; nb++) {
                    uint32_t r[4];
                    ldmatrix_x4(r, Bb + sw_off(b_row + nb * 16, bc));
                    b[nb * 2][0] = r[0]; b[nb * 2][1] = r[1];
                    b[nb * 2 + 1][0] = r[2]; b[nb * 2 + 1][1] = r[3];
                }
                #pragma unroll
                for (int mf = 0; mf < 2; mf++)
                    #pragma unroll
                    for (int nf = 0; nf < 8; nf++)
                        mma16816(acc[mf][nf], a[mf], b[nf]);
            }
        }
        if (++stage >= NSTAGE) stage = 0;
    }

    #pragma unroll
    for (int mf = 0; mf < 2; mf++) {
        const int r0 = m0 + wm * 32 + mf * 16 + (lane >> 2);
        #pragma unroll
        for (int nf = 0; nf < 8; nf++) {
            const int col = n0 + wn * 64 + nf * 8 + (lane & 3) * 2;
            if (col < N) {
                float2 v0 = make_float2(acc[mf][nf][0], acc[mf][nf][1]);
                float2 v1 = make_float2(acc[mf][nf][2], acc[mf][nf][3]);
                *reinterpret_cast<float2*>(&C[(size_t)r0 * N + col]) = v0;
                *reinterpret_cast<float2*>(&C[(size_t)(r0 + 8) * N + col]) = v1;
            }
        }
    }
}

// ---------------- K1: segmented scan with fused conv+SiLU --------------------
__global__ __launch_bounds__(128)
void seg_scan_kernel(const float* __restrict__ proj,
                     const float* __restrict__ conv_w,
                     const float* __restrict__ conv_b,
                     const float* __restrict__ A_log,
                     const float* __restrict__ dt_bias,
                     float* __restrict__ xconv,
                     float* __restrict__ ypart,
                     float* __restrict__ decay,
                     float* __restrict__ hseg,
                     float* __restrict__ aprod)
{
    const int blk = blockIdx.x;
    const int bh  = blk >> 5;
    const int rem = blk & 31;
    const int seg = rem >> 1;
    const int dg  = rem & 1;
    const int b   = bh / NHEADS;
    const int n   = bh % NHEADS;
    const int tid = threadIdx.x;
    const int dl  = tid >> 2;
    const int q   = tid & 3;
    const int d   = dg * 32 + dl;
    const int c   = n * HEADDIM + d;
    const int t0  = seg * LSEG;

    __shared__ float sA[2][D_STATE];
    __shared__ float sB[2][D_STATE];
    __shared__ float sC[2][D_STATE];

    float negA = 0.f;
    if (tid < D_STATE) negA = -expf(A_log[n * D_STATE + tid]);
    const float dtb = dt_bias[n];

    const float cw0 = conv_w[c * D_CONV + 0];
    const float cw1 = conv_w[c * D_CONV + 1];
    const float cw2 = conv_w[c * D_CONV + 2];
    const float cw3 = conv_w[c * D_CONV + 3];
    const float cb  = conv_b[c];

    const float* projB = proj + (size_t)(b * SEQLEN + t0) * D_PROJ;
    const float* bcB   = projB + 2 * D_INNER + n * (2 * D_STATE + 1);
    const float* xiB   = projB + c;
    float* decB  = decay + ((size_t)bh * SEQLEN + t0) * D_STATE;
    float* ypB   = ypart + ((size_t)bh * SEQLEN + t0) * HEADDIM + d;
    float* xcB   = xconv + (size_t)(b * SEQLEN + t0) * D_INNER + c;

    float pB[4], pC[4], pDt[4], pXI[4];
    float xw0, xw1, xw2, xw3;
    float r = 1.f;

    {   // prologue
        #pragma unroll
        for (int s = 0; s < 4; s++) {
            if (tid < D_STATE) {
                const float* bc = bcB + (size_t)s * D_PROJ;
                pB[s]  = bc[tid];
                pC[s]  = bc[D_STATE + tid];
                pDt[s] = bc[2 * D_STATE];
            }
        }
        xw0 = (t0 >= 3) ? xiB[(size_t)(-3) * D_PROJ] : 0.f;
        xw1 = (t0 >= 2) ? xiB[(size_t)(-2) * D_PROJ] : 0.f;
        xw2 = (t0 >= 1) ? xiB[(size_t)(-1) * D_PROJ] : 0.f;
        xw3 = xiB[0];
        pXI[1] = xiB[(size_t)1 * D_PROJ];
        pXI[2] = xiB[(size_t)2 * D_PROJ];
        pXI[3] = xiB[(size_t)3 * D_PROJ];
        pXI[0] = 0.f;
        if (tid < D_STATE) {
            float dtr = pDt[0] + dtb;
            float dt  = fmaxf(dtr, 0.f) + log1pf(expf(-fabsf(dtr)));
            float a   = expf(negA * dt);
            sA[0][tid] = a;
            sB[0][tid] = pB[0] * dt;
            sC[0][tid] = pC[0];
            r = a;
            if (dg == 0) decB[tid] = r;
        }
    }
    __syncthreads();

    float h[16];
    #pragma unroll
    for (int i = 0; i < 16; i++) h[i] = 0.f;

    const int s0 = q * 16;
    int buf = 0;

    #pragma unroll 4
    for (int t = 0; t < LSEG; t++) {
        const int slot  = t & 3;
        const int nslot = (t + 1) & 3;

        float xc = cb;
        xc = fmaf(cw0, xw0, xc);
        xc = fmaf(cw1, xw1, xc);
        xc = fmaf(cw2, xw2, xc);
        xc = fmaf(cw3, xw3, xc);
        const float xv = xc / (1.f + expf(-xc));

        if (t + 1 < LSEG && tid < D_STATE) {
            float dtr = pDt[nslot] + dtb;
            float dt  = fmaxf(dtr, 0.f) + log1pf(expf(-fabsf(dtr)));
            float a   = expf(negA * dt);
            sA[buf ^ 1][tid] = a;
            sB[buf ^ 1][tid] = pB[nslot] * dt;
            sC[buf ^ 1][tid] = pC[nslot];
            r *= a;
            if (dg == 0) decB[(size_t)(t + 1) * D_STATE + tid] = r;
        }

        if (t + 4 < LSEG) {
            const int tp = t + 4;
            if (tid < D_STATE) {
                const float* bc = bcB + (size_t)tp * D_PROJ;
                pB[slot]  = bc[tid];
                pC[slot]  = bc[D_STATE + tid];
                pDt[slot] = bc[2 * D_STATE];
            }
            pXI[slot] = xiB[(size_t)tp * D_PROJ];
        }

        float a0 = 0.f, a1 = 0.f, a2 = 0.f, a3 = 0.f;
        #pragma unroll
        for (int j4 = 0; j4 < 4; j4++) {
            float4 a4 = *reinterpret_cast<const float4*>(&sA[buf][s0 + j4 * 4]);
            float4 b4 = *reinterpret_cast<const float4*>(&sB[buf][s0 + j4 * 4]);
            float4 c4 = *reinterpret_cast<const float4*>(&sC[buf][s0 + j4 * 4]);
            h[j4*4+0] = fmaf(a4.x, h[j4*4+0], b4.x * xv);
            h[j4*4+1] = fmaf(a4.y, h[j4*4+1], b4.y * xv);
            h[j4*4+2] = fmaf(a4.z, h[j4*4+2], b4.z * xv);
            h[j4*4+3] = fmaf(a4.w, h[j4*4+3], b4.w * xv);
            a0 = fmaf(c4.x, h[j4*4+0], a0);
            a1 = fmaf(c4.y, h[j4*4+1], a1);
            a2 = fmaf(c4.z, h[j4*4+2], a2);
            a3 = fmaf(c4.w, h[j4*4+3], a3);
        }
        float accv = (a0 + a1) + (a2 + a3);
        accv += __shfl_xor_sync(0xFFFFFFFFu, accv, 1);
        accv += __shfl_xor_sync(0xFFFFFFFFu, accv, 2);

        if (q == 0) {
            ypB[(size_t)t * HEADDIM] = accv;
            xcB[(size_t)t * D_INNER] = xv;
        }
        xw0 = xw1; xw1 = xw2; xw2 = xw3; xw3 = pXI[nslot];
        __syncthreads();
        buf ^= 1;
    }

    float* hs = hseg + (((size_t)bh * NSEG + seg) * D_STATE) * HEADDIM;
    #pragma unroll
    for (int j = 0; j < 16; j++)
        hs[(size_t)(s0 + j) * HEADDIM + d] = h[j];

    if (dg == 0 && tid < D_STATE)
        aprod[((size_t)bh * NSEG + seg) * D_STATE + tid] = r;
}

// ---------------- K2: combine segment states (pipelined) ---------------------
// grid NBH, 512 threads: d = tid&63, g = tid>>6 (8 states each).
// Depth-1 register prefetch of next segment's hseg/aprod hides DRAM latency.
__global__ __launch_bounds__(512)
void combine_kernel(const float* __restrict__ hseg,
                    const float* __restrict__ aprod,
                    float* __restrict__ hstart)
{
    const int bh  = blockIdx.x;
    const int tid = threadIdx.x;
    const int d   = tid & 63;
    const int sb  = (tid >> 6) * 8;       // states sb..sb+7

    float hs[8];
    #pragma unroll
    for (int j = 0; j < 8; j++) hs[j] = 0.f;

    // segment 0 starts from zero
    {
        float* dst = hstart + (((size_t)bh * NSEG) * D_STATE) * HEADDIM;
        #pragma unroll
        for (int j = 0; j < 8; j++)
            dst[(size_t)(sb + j) * HEADDIM + d] = 0.f;
    }

    // prefetch segment 0 contribution
    float ph[8], pa[8];
    {
        const size_t p0 = (size_t)bh * NSEG;
        const float* hp = hseg + p0 * D_STATE * HEADDIM;
        const float* ap = aprod + p0 * D_STATE;
        #pragma unroll
        for (int j = 0; j < 8; j++) {
            ph[j] = hp[(size_t)(sb + j) * HEADDIM + d];
            pa[j] = ap[sb + j];
        }
    }

    for (int seg = 1; seg < NSEG; seg++) {
        float ch[8], ca[8];
        #pragma unroll
        for (int j = 0; j < 8; j++) { ch[j] = ph[j]; ca[j] = pa[j]; }

        if (seg < NSEG - 1) {     // prefetch segment `seg` contribution
            const size_t pn = (size_t)bh * NSEG + seg;
            const float* hp = hseg + pn * D_STATE * HEADDIM;
            const float* ap = aprod + pn * D_STATE;
            #pragma unroll
            for (int j = 0; j < 8; j++) {
                ph[j] = hp[(size_t)(sb + j) * HEADDIM + d];
                pa[j] = ap[sb + j];
            }
        }

        float* dst = hstart + (((size_t)bh * NSEG + seg) * D_STATE) * HEADDIM;
        #pragma unroll
        for (int j = 0; j < 8; j++) {
            hs[j] = fmaf(ca[j], hs[j], ch[j]);
            dst[(size_t)(sb + j) * HEADDIM + d] = hs[j];
        }
    }
}

// ---------------- K3: fixup + skip + gate + bf16 split -----------------------
// grid 1024 = (bh, seg), 256 threads = 4 token slots x 64 d; depth-1 register
// prefetch of next iteration's streams.
__global__ __launch_bounds__(256)
void fixup_kernel(const float* __restrict__ proj,
                  const float* __restrict__ xconv,
                  const float* __restrict__ ypart,
                  const float* __restrict__ decay,
                  const float* __restrict__ hstart,
                  const float* __restrict__ Dp,
                  __nv_bfloat16* __restrict__ y_hi,
                  __nv_bfloat16* __restrict__ y_lo)
{
    const int blk = blockIdx.x;
    const int bh  = blk >> 4;
    const int seg = blk & 15;
    const int b   = bh / NHEADS;
    const int n   = bh % NHEADS;
    const int t0  = seg * LSEG;
    const int tid = threadIdx.x;
    const int tt  = tid >> 6;            // token slot 0..3
    const int d   = tid & 63;
    const float Dn = Dp[n];

    __shared__ float h0[D_STATE * HEADDIM];
    __shared__ float w[4][D_STATE];

    {
        const float* src = hstart + (((size_t)bh * NSEG + seg) * D_STATE) * HEADDIM;
        for (int i = tid; i < D_STATE * HEADDIM; i += 256)
            h0[i] = src[i];
    }

    // per-iteration stream prefetch registers (iteration = 4 tokens)
    float pCs, pDec, pYp, pXv, pZv;
    {
        const int t = t0 + tt;
        const float* bc = proj + (size_t)(b * SEQLEN + t) * D_PROJ
                          + 2 * D_INNER + n * (2 * D_STATE + 1);
        pCs  = bc[D_STATE + d];
        pDec = decay[((size_t)bh * SEQLEN + t) * D_STATE + d];
        pYp  = ypart[((size_t)bh * SEQLEN + t) * HEADDIM + d];
        pXv  = xconv[(size_t)(b * SEQLEN + t) * D_INNER + n * HEADDIM + d];
        pZv  = proj[(size_t)(b * SEQLEN + t) * D_PROJ + D_INNER + n * HEADDIM + d];
    }
    __syncthreads();

    for (int ti = 0; ti < LSEG; ti += 4) {
        const int t = t0 + ti + tt;
        const float yp = pYp, xv = pXv, zv = pZv;
        w[tt][d] = pCs * pDec;
        __syncthreads();

        // prefetch next iteration's streams
        if (ti + 4 < LSEG) {
            const int tn = t + 4;
            const float* bc = proj + (size_t)(b * SEQLEN + tn) * D_PROJ
                              + 2 * D_INNER + n * (2 * D_STATE + 1);
            pCs  = bc[D_STATE + d];
            pDec = decay[((size_t)bh * SEQLEN + tn) * D_STATE + d];
            pYp  = ypart[((size_t)bh * SEQLEN + tn) * HEADDIM + d];
            pXv  = xconv[(size_t)(b * SEQLEN + tn) * D_INNER + n * HEADDIM + d];
            pZv  = proj[(size_t)(b * SEQLEN + tn) * D_PROJ + D_INNER + n * HEADDIM + d];
        }

        float a0 = 0.f, a1 = 0.f, a2 = 0.f, a3 = 0.f;
        #pragma unroll
        for (int s = 0; s < D_STATE; s += 4) {
            a0 = fmaf(w[tt][s + 0], h0[(s + 0) * HEADDIM + d], a0);
            a1 = fmaf(w[tt][s + 1], h0[(s + 1) * HEADDIM + d], a1);
            a2 = fmaf(w[tt][s + 2], h0[(s + 2) * HEADDIM + d], a2);
            a3 = fmaf(w[tt][s + 3], h0[(s + 3) * HEADDIM + d], a3);
        }
        float yfix = (a0 + a1) + (a2 + a3);

        float yv = yp + yfix + Dn * xv;
        float o  = yv * (zv / (1.f + expf(-zv)));
        __nv_bfloat16 oh = __float2bfloat16(o);
        size_t oi = (size_t)(b * SEQLEN + t) * D_INNER + n * HEADDIM + d;
        y_hi[oi] = oh;
        y_lo[oi] = __float2bfloat16(o - __bfloat162float(oh));
        __syncthreads();   // protect w before next iteration's write
    }
}

// ---------------- launcher ---------------------------------------------------
extern "C" void kernel_launch(void* const* d_in, const int* in_sizes, int n_in,
                              void* d_out, int out_size)
{
    const float* x       = (const float*)d_in[0];
    const float* W_in    = (const float*)d_in[1];
    const float* conv_w  = (const float*)d_in[2];
    const float* conv_b  = (const float*)d_in[3];
    const float* A_log   = (const float*)d_in[4];
    const float* Dp      = (const float*)d_in[5];
    const float* dt_bias = (const float*)d_in[6];
    const float* W_out   = (const float*)d_in[7];
    float* out = (float*)d_out;

    float *proj, *xconv, *ypart, *decay, *hseg, *hstart, *aprod;
    __nv_bfloat16 *xh, *xl, *wih, *wil, *woh, *wol, *yh, *yl;
    cudaGetSymbolAddress((void**)&proj,   g_proj);
    cudaGetSymbolAddress((void**)&xconv,  g_xconv);
    cudaGetSymbolAddress((void**)&ypart,  g_ypart);
    cudaGetSymbolAddress((void**)&decay,  g_decay);
    cudaGetSymbolAddress((void**)&hseg,   g_hseg);
    cudaGetSymbolAddress((void**)&hstart, g_hstart);
    cudaGetSymbolAddress((void**)&aprod,  g_aprod);
    cudaGetSymbolAddress((void**)&xh,  g_x_hi);    cudaGetSymbolAddress((void**)&xl,  g_x_lo);
    cudaGetSymbolAddress((void**)&wih, g_Win_hi);  cudaGetSymbolAddress((void**)&wil, g_Win_lo);
    cudaGetSymbolAddress((void**)&woh, g_Wout_hi); cudaGetSymbolAddress((void**)&wol, g_Wout_lo);
    cudaGetSymbolAddress((void**)&yh,  g_y_hi);    cudaGetSymbolAddress((void**)&yl,  g_y_lo);

    cudaFuncSetAttribute(gemm_mma, cudaFuncAttributeMaxDynamicSharedMemorySize, GEMM_SMEM);

    // 0) fused fp32 -> bf16 hi/lo splits
    {
        long total = (long)NX_ELEM + NWP_ELEM + NWO_ELEM;
        split_all<<<(int)((total + 255) / 256), 256>>>(x, W_in, W_out,
                                                       xh, xl, wih, wil, woh, wol);
    }
    // 1) proj = x @ W_in^T
    {
        dim3 grid(NPROJ_PAD / 128, NTOK / 128);
        gemm_mma<<<grid, 256, GEMM_SMEM>>>(xh, xl, wih, wil, proj, NTOK, D_PROJ, D_MODEL);
    }
    // 2) segmented scan (conv fused): K1 -> K2 -> K3
    {
        seg_scan_kernel<<<NBH * NSEG * 2, 128>>>(proj, conv_w, conv_b, A_log, dt_bias,
                                                 xconv, ypart, decay, hseg, aprod);
        combine_kernel<<<NBH, 512>>>(hseg, aprod, hstart);
        fixup_kernel<<<NBH * NSEG, 256>>>(proj, xconv, ypart, decay, hstart, Dp, yh, yl);
    }
    // 3) out = y @ W_out^T
    {
        dim3 grid(D_MODEL / 128, NTOK / 128);
        gemm_mma<<<grid, 256, GEMM_SMEM>>>(yh, yl, woh, wol, out, NTOK, D_MODEL, D_INNER);
    }
}